// round 7
// baseline (speedup 1.0000x reference)
#include <cuda_runtime.h>
#include <cuda_bf16.h>
#include <math.h>
#include <stdint.h>

#define B_SZ   2048
#define K_OBJ  16
#define ROWS   (B_SZ * K_OBJ)      // 32768
#define NPAIR  120

typedef __nv_bfloat16 bf16;

// ---------------- scratch (device globals; no allocation allowed) ----------------
__device__ __align__(16) bf16 g_z_hi  [(size_t)ROWS * 128];
__device__ __align__(16) bf16 g_z_lo  [(size_t)ROWS * 128];
__device__ __align__(16) bf16 g_h0_hi [(size_t)ROWS * 128];
__device__ __align__(16) bf16 g_h0_lo [(size_t)ROWS * 128];
__device__ __align__(16) bf16 g_ze_hi [(size_t)ROWS * 256];
__device__ __align__(16) bf16 g_ze_lo [(size_t)ROWS * 256];
__device__ __align__(16) bf16 g_h_hi  [(size_t)ROWS * 128];
__device__ __align__(16) bf16 g_h_lo  [(size_t)ROWS * 128];
__device__ __align__(16) bf16 g_E_hi  [(size_t)ROWS * 512];
__device__ __align__(16) bf16 g_E_lo  [(size_t)ROWS * 512];
__device__ __align__(16) bf16 g_rel_hi[(size_t)ROWS * 128];
__device__ __align__(16) bf16 g_rel_lo[(size_t)ROWS * 128];
__device__ __align__(16) float g_gi [(size_t)ROWS * 384];
__device__ __align__(16) float g_gh [(size_t)ROWS * 384];
__device__ __align__(16) float g_UV [(size_t)ROWS * 1024];
__device__ __align__(16) bf16 g_Wobj_hi[256 * 128],  g_Wobj_lo[256 * 128];
__device__ __align__(16) bf16 g_Wih_hi [384 * 256],  g_Wih_lo [384 * 256];
__device__ __align__(16) bf16 g_Whh_hi [384 * 128],  g_Whh_lo [384 * 128];
__device__ __align__(16) bf16 g_WUV_hi [1024 * 128], g_WUV_lo [1024 * 128];
__device__ __align__(16) bf16 g_WcE_hi [128 * 640],  g_WcE_lo [128 * 640];
__device__ __align__(16) bf16 g_Wstk_hi[384 * 128],  g_Wstk_lo[384 * 128];
__device__ __align__(16) float g_bstk[384];

// ---------------- helpers ----------------
__device__ __forceinline__ void bf16split(float x, bf16& h, bf16& l) {
    h = __float2bfloat16_rn(x);
    l = __float2bfloat16_rn(x - __bfloat162float(h));
}

__device__ __forceinline__ uint32_t smem_u32(const void* p) {
    uint32_t a;
    asm("{ .reg .u64 t; cvta.to.shared.u64 t, %1; cvt.u32.u64 %0, t; }" : "=r"(a) : "l"(p));
    return a;
}

__device__ __forceinline__ void cp16(uint32_t dst, const void* src) {
    asm volatile("cp.async.ca.shared.global [%0], [%1], 16;" :: "r"(dst), "l"(src) : "memory");
}
#define CP_COMMIT() asm volatile("cp.async.commit_group;" ::: "memory")
#define CP_WAIT(n)  asm volatile("cp.async.wait_group %0;" :: "n"(n) : "memory")

__device__ __forceinline__ void mma16(float* d, const uint32_t* a, const uint32_t* b) {
    asm volatile(
        "mma.sync.aligned.m16n8k16.row.col.f32.bf16.bf16.f32 "
        "{%0,%1,%2,%3}, {%4,%5,%6,%7}, {%8,%9}, {%0,%1,%2,%3};"
        : "+f"(d[0]), "+f"(d[1]), "+f"(d[2]), "+f"(d[3])
        : "r"(a[0]), "r"(a[1]), "r"(a[2]), "r"(a[3]), "r"(b[0]), "r"(b[1]));
}

__device__ __forceinline__ void ldm_x4(uint32_t* r, uint32_t addr) {
    asm volatile("ldmatrix.sync.aligned.m8n8.x4.shared.b16 {%0,%1,%2,%3}, [%4];"
        : "=r"(r[0]), "=r"(r[1]), "=r"(r[2]), "=r"(r[3]) : "r"(addr));
}

// ---------------- tensor-core bf16x3 NT GEMM (R5 structure + ldmatrix) ----------------
#define PADW 12
#define TILE_WORDS 1536    // 128 * PADW
#define STG_WORDS  6144    // 4 tiles * TILE_WORDS
#define TILE_BYTES (TILE_WORDS * 4)
#define STG_BYTES  (STG_WORDS * 4)

template <int ACT, int OUTM>
__global__ void __launch_bounds__(256, 2) gemm_mma(
    const bf16* __restrict__ X1hi, const bf16* __restrict__ X1lo, int ld1, int k1,
    const bf16* __restrict__ X2hi, const bf16* __restrict__ X2lo, int ld2,
    const bf16* __restrict__ Whi, const bf16* __restrict__ Wlo,
    const float* __restrict__ bias,
    float* __restrict__ C, bf16* __restrict__ Chi, bf16* __restrict__ Clo,
    int ldc, float* __restrict__ C2, int Kd)
{
    extern __shared__ uint32_t smw[];
    const uint32_t sb = smem_u32(smw);

    const int tid = threadIdx.x;
    const int lane = tid & 31;
    const int wid = tid >> 5;
    const int warp_m = wid >> 1;
    const int warp_n = wid & 1;
    const int gid = lane >> 2;
    const int tig = lane & 3;
    const int bm = blockIdx.y * 128;
    const int bn = blockIdx.x * 128;

    float acc[2][8][4];
#pragma unroll
    for (int mi = 0; mi < 2; mi++)
#pragma unroll
        for (int nf = 0; nf < 8; nf++)
#pragma unroll
            for (int e = 0; e < 4; e++) acc[mi][nf][e] = 0.f;

    const int lm = tid >> 1;
    const int lk = (tid & 1) * 8;
    const uint32_t so = (uint32_t)(lm * PADW + (tid & 1) * 4) * 4;

    // ldmatrix lane offsets (byte offsets within a tile)
    const uint32_t aoff = (uint32_t)((warp_m * 32 + (lane & 15)) * PADW + 4 * (lane >> 4)) * 4;
    const uint32_t boff = (uint32_t)((warp_n * 64 + (lane & 7) + 8 * (lane >> 4)) * PADW
                                     + 4 * ((lane >> 3) & 1)) * 4;

    auto load_slab = [&](int k0, int s) {
        const bf16 *ahi, *alo; int xld, xc;
        if (k0 < k1) { ahi = X1hi; alo = X1lo; xld = ld1; xc = k0; }
        else         { ahi = X2hi; alo = X2lo; xld = ld2; xc = k0 - k1; }
        const uint32_t st = sb + s * STG_BYTES;
        const size_t ga = (size_t)(bm + lm) * xld + xc + lk;
        const size_t gw = (size_t)(bn + lm) * Kd + k0 + lk;
        cp16(st + so,                  ahi + ga);
        cp16(st + TILE_BYTES + so,     alo + ga);
        cp16(st + 2 * TILE_BYTES + so, Whi + gw);
        cp16(st + 3 * TILE_BYTES + so, Wlo + gw);
    };

    int s = 0;
    load_slab(0, 0);
    CP_COMMIT();

#pragma unroll 1
    for (int k0 = 0; k0 < Kd; k0 += 16) {
        if (k0 + 16 < Kd) {
            load_slab(k0 + 16, s ^ 1);
            CP_COMMIT();
            CP_WAIT(1);
        } else {
            CP_WAIT(0);
        }
        __syncthreads();

        const uint32_t st = sb + s * STG_BYTES;

        uint32_t ah[2][4], al[2][4], bfr[16];
        ldm_x4(ah[0], st + aoff);
        ldm_x4(ah[1], st + aoff + 16 * PADW * 4);
        ldm_x4(al[0], st + TILE_BYTES + aoff);
        ldm_x4(al[1], st + TILE_BYTES + aoff + 16 * PADW * 4);
#pragma unroll
        for (int j = 0; j < 4; j++)
            ldm_x4(&bfr[4 * j], st + 2 * TILE_BYTES + boff + j * 16 * PADW * 4);

#pragma unroll
        for (int mi = 0; mi < 2; mi++)
#pragma unroll
            for (int nf = 0; nf < 8; nf++) {
                mma16(acc[mi][nf], ah[mi], &bfr[nf * 2]);
                mma16(acc[mi][nf], al[mi], &bfr[nf * 2]);
            }
#pragma unroll
        for (int j = 0; j < 4; j++)
            ldm_x4(&bfr[4 * j], st + 3 * TILE_BYTES + boff + j * 16 * PADW * 4);
#pragma unroll
        for (int mi = 0; mi < 2; mi++)
#pragma unroll
            for (int nf = 0; nf < 8; nf++)
                mma16(acc[mi][nf], ah[mi], &bfr[nf * 2]);

        __syncthreads();
        s ^= 1;
    }

    // ---- epilogue ----
    float* outp = C; int oldc = ldc, ncol0 = bn;
    if (OUTM == 2) {
        if (bn >= 256) { outp = C2; oldc = 128; ncol0 = bn - 256; }
        else           { outp = C;  oldc = 256; ncol0 = bn; }
    }

#pragma unroll
    for (int mi = 0; mi < 2; mi++) {
        int r0 = bm + warp_m * 32 + mi * 16 + gid;
#pragma unroll
        for (int nf = 0; nf < 8; nf++) {
            int cg = bn + warp_n * 64 + nf * 8 + tig * 2;
            int cl = ncol0 + warp_n * 64 + nf * 8 + tig * 2;
            float b0 = 0.f, b1 = 0.f;
            if (bias) { float2 bv = *(const float2*)(bias + cg); b0 = bv.x; b1 = bv.y; }
            float v00 = acc[mi][nf][0] + b0;
            float v01 = acc[mi][nf][1] + b1;
            float v10 = acc[mi][nf][2] + b0;
            float v11 = acc[mi][nf][3] + b1;
            if (ACT == 1) {
                v00 = (v00 > 0.f) ? v00 : expm1f(v00);
                v01 = (v01 > 0.f) ? v01 : expm1f(v01);
                v10 = (v10 > 0.f) ? v10 : expm1f(v10);
                v11 = (v11 > 0.f) ? v11 : expm1f(v11);
            }
            if (OUTM == 1) {
                bf16 h, l;
                __nv_bfloat162 ph0, pl0, ph1, pl1;
                bf16split(v00, h, l); ph0.x = h; pl0.x = l;
                bf16split(v01, h, l); ph0.y = h; pl0.y = l;
                bf16split(v10, h, l); ph1.x = h; pl1.x = l;
                bf16split(v11, h, l); ph1.y = h; pl1.y = l;
                *(__nv_bfloat162*)(Chi + (size_t)r0 * ldc + cl)       = ph0;
                *(__nv_bfloat162*)(Clo + (size_t)r0 * ldc + cl)       = pl0;
                *(__nv_bfloat162*)(Chi + (size_t)(r0 + 8) * ldc + cl) = ph1;
                *(__nv_bfloat162*)(Clo + (size_t)(r0 + 8) * ldc + cl) = pl1;
            } else {
                *(float2*)(outp + (size_t)r0 * oldc + cl)       = make_float2(v00, v01);
                *(float2*)(outp + (size_t)(r0 + 8) * oldc + cl) = make_float2(v10, v11);
            }
        }
    }
}

// ---------------- split / prep kernels ----------------
__global__ void split_f32(const float* __restrict__ src, bf16* __restrict__ hi,
                          bf16* __restrict__ lo, int n) {
    int idx = blockIdx.x * blockDim.x + threadIdx.x;
    if (idx >= n) return;
    bf16 h, l;
    bf16split(src[idx], h, l);
    hi[idx] = h; lo[idx] = l;
}

__global__ void prep_wuv(const float* __restrict__ We) {
    int idx = blockIdx.x * blockDim.x + threadIdx.x;
    if (idx >= 1024 * 128) return;
    int n = idx >> 7, c = idx & 127;
    float v;
    if (n < 512) v = We[n * 512 + c] + We[n * 512 + 128 + c];
    else {
        int nn = n - 512;
        v = We[nn * 512 + 256 + c] + We[nn * 512 + 384 + c];
    }
    bf16 h, l; bf16split(v, h, l);
    g_WUV_hi[idx] = h; g_WUV_lo[idx] = l;
}

__global__ void prep_wc(const float* __restrict__ Wc) {
    int idx = blockIdx.x * blockDim.x + threadIdx.x;
    if (idx >= 128 * 640) return;
    int n = idx / 640, c = idx % 640;
    float v = (c < 128) ? (Wc[n * 768 + c] + Wc[n * 768 + 128 + c])
                        : Wc[n * 768 + 128 + c];
    bf16 h, l; bf16split(v, h, l);
    g_WcE_hi[idx] = h; g_WcE_lo[idx] = l;
}

__global__ void prep_wstk(const float* __restrict__ Wl, const float* __restrict__ bl,
                          const float* __restrict__ Wsc, const float* __restrict__ bs,
                          const float* __restrict__ Wh, const float* __restrict__ bh) {
    int idx = blockIdx.x * blockDim.x + threadIdx.x;
    if (idx < 384 * 128) {
        int n = idx >> 7, c = idx & 127;
        const float* W = (n < 128) ? Wl : ((n < 256) ? Wsc : Wh);
        bf16 h, l; bf16split(W[(n & 127) * 128 + c], h, l);
        g_Wstk_hi[idx] = h; g_Wstk_lo[idx] = l;
    }
    if (idx < 384) {
        const float* bb = (idx < 128) ? bl : ((idx < 256) ? bs : bh);
        g_bstk[idx] = bb[idx & 127];
    }
}

// ---------------- GRU gate fusion (writes split h) ----------------
__device__ __forceinline__ float sigm(float x) { return 1.f / (1.f + expf(-x)); }

__global__ void gru_gate(const float* __restrict__ gi, const float* __restrict__ gh,
                         const float* __restrict__ h0,
                         bf16* __restrict__ hhi, bf16* __restrict__ hlo) {
    int idx = blockIdx.x * blockDim.x + threadIdx.x;
    if (idx >= ROWS * 128) return;
    int m = idx >> 7, c = idx & 127;
    const float* gim = gi + (size_t)m * 384;
    const float* ghm = gh + (size_t)m * 384;
    float r = sigm(gim[c] + ghm[c]);
    float u = sigm(gim[128 + c] + ghm[128 + c]);
    float n = tanhf(gim[256 + c] + r * ghm[256 + c]);
    float v = (1.f - u) * n + u * h0[idx];
    bf16 h, l; bf16split(v, h, l);
    hhi[idx] = h; hlo[idx] = l;
}

// ---------------- pair stage: warp-per-object, atomic-free ----------------
// Warp w accumulates E[w] over all 15 pairs containing object w, recomputing
// eff per endpoint. E held in registers; U_w, V_w, be, Wa hoisted to registers.
__global__ void __launch_bounds__(512) pair_kernel(
    const float* __restrict__ UV, const float* __restrict__ Wa,
    const float* __restrict__ ba, const float* __restrict__ be,
    bf16* __restrict__ Ehi, bf16* __restrict__ Elo)
{
    extern __shared__ float smf[];
    float* Ub = smf;                 // 16*512
    float* Vb = Ub + 16 * 512;       // 16*512

    const int b = blockIdx.x;
    const int tid = threadIdx.x;
    const int w = tid >> 5, lane = tid & 31;

    for (int i = tid; i < 16 * 512; i += 512) {
        int k = i >> 9, t = i & 511;
        const float* row = UV + (size_t)(b * 16 + k) * 1024;
        Ub[i] = row[t];
        Vb[i] = row[512 + t];
    }
    __syncthreads();

    const float ba0 = __ldg(&ba[0]);
    float uw[16], vw[16], ber[16], war[16], Ew[16];
#pragma unroll
    for (int c = 0; c < 16; c++) {
        int t = lane + 32 * c;
        uw[c] = Ub[w * 512 + t];
        vw[c] = Vb[w * 512 + t];
        ber[c] = __ldg(&be[t]);
        war[c] = __ldg(&Wa[t]);
        Ew[c] = 0.f;
    }

#pragma unroll 1
    for (int o = 0; o < K_OBJ; o++) {
        if (o == w) continue;
        const float* Urow = Ub + o * 512;   // used when o < w (pair (o,w))
        const float* Vrow = Vb + o * 512;   // used when o > w (pair (w,o))
        float e[16];
        float dot = 0.f;
        if (o > w) {
#pragma unroll
            for (int c = 0; c < 16; c++) {
                float x = uw[c] + Vrow[lane + 32 * c] + ber[c];
                x = (x > 0.f) ? x : expm1f(x);
                e[c] = x;
                dot += x * war[c];
            }
        } else {
#pragma unroll
            for (int c = 0; c < 16; c++) {
                float x = Urow[lane + 32 * c] + vw[c] + ber[c];
                x = (x > 0.f) ? x : expm1f(x);
                e[c] = x;
                dot += x * war[c];
            }
        }
#pragma unroll
        for (int off = 16; off > 0; off >>= 1) dot += __shfl_xor_sync(0xffffffffu, dot, off);
        float att = 1.f / (1.f + expf(-(dot + ba0)));
#pragma unroll
        for (int c = 0; c < 16; c++) Ew[c] += att * e[c];
    }

    bf16* Eh = Ehi + ((size_t)b * 16 + w) * 512;
    bf16* El = Elo + ((size_t)b * 16 + w) * 512;
#pragma unroll
    for (int c = 0; c < 16; c++) {
        bf16 h, l; bf16split(Ew[c], h, l);
        Eh[lane + 32 * c] = h;
        El[lane + 32 * c] = l;
    }
}

// ---------------- host launcher ----------------
extern "C" void kernel_launch(void* const* d_in, const int* in_sizes, int n_in,
                              void* d_out, int out_size)
{
    const float* z    = (const float*)d_in[0];
    const float* h0   = (const float*)d_in[1];
    const float* W_obj= (const float*)d_in[2];
    const float* b_obj= (const float*)d_in[3];
    const float* Wih  = (const float*)d_in[4];
    const float* bih  = (const float*)d_in[5];
    const float* Whh  = (const float*)d_in[6];
    const float* bhh  = (const float*)d_in[7];
    const float* We   = (const float*)d_in[8];
    const float* be   = (const float*)d_in[9];
    const float* Wa   = (const float*)d_in[10];
    const float* ba   = (const float*)d_in[11];
    const float* Wc   = (const float*)d_in[12];
    const float* bc   = (const float*)d_in[13];
    const float* Wl   = (const float*)d_in[14];
    const float* bl   = (const float*)d_in[15];
    const float* Wsc  = (const float*)d_in[16];
    const float* bs   = (const float*)d_in[17];
    const float* Wh   = (const float*)d_in[18];
    const float* bh   = (const float*)d_in[19];

    float* out1 = (float*)d_out;                 // [ROWS, 256] = concat(loc, scale)
    float* out2 = out1 + (size_t)ROWS * 256;     // [ROWS, 128] = h_out

    bf16 *p_z_hi, *p_z_lo, *p_h0_hi, *p_h0_lo, *p_ze_hi, *p_ze_lo;
    bf16 *p_h_hi, *p_h_lo, *p_E_hi, *p_E_lo, *p_rel_hi, *p_rel_lo;
    float *p_gi, *p_gh, *p_UV, *p_bstk;
    bf16 *p_Wobj_hi, *p_Wobj_lo, *p_Wih_hi, *p_Wih_lo, *p_Whh_hi, *p_Whh_lo;
    bf16 *p_WUV_hi, *p_WUV_lo, *p_WcE_hi, *p_WcE_lo, *p_Wstk_hi, *p_Wstk_lo;

    cudaGetSymbolAddress((void**)&p_z_hi,  g_z_hi);   cudaGetSymbolAddress((void**)&p_z_lo,  g_z_lo);
    cudaGetSymbolAddress((void**)&p_h0_hi, g_h0_hi);  cudaGetSymbolAddress((void**)&p_h0_lo, g_h0_lo);
    cudaGetSymbolAddress((void**)&p_ze_hi, g_ze_hi);  cudaGetSymbolAddress((void**)&p_ze_lo, g_ze_lo);
    cudaGetSymbolAddress((void**)&p_h_hi,  g_h_hi);   cudaGetSymbolAddress((void**)&p_h_lo,  g_h_lo);
    cudaGetSymbolAddress((void**)&p_E_hi,  g_E_hi);   cudaGetSymbolAddress((void**)&p_E_lo,  g_E_lo);
    cudaGetSymbolAddress((void**)&p_rel_hi,g_rel_hi); cudaGetSymbolAddress((void**)&p_rel_lo,g_rel_lo);
    cudaGetSymbolAddress((void**)&p_gi, g_gi);
    cudaGetSymbolAddress((void**)&p_gh, g_gh);
    cudaGetSymbolAddress((void**)&p_UV, g_UV);
    cudaGetSymbolAddress((void**)&p_bstk, g_bstk);
    cudaGetSymbolAddress((void**)&p_Wobj_hi, g_Wobj_hi); cudaGetSymbolAddress((void**)&p_Wobj_lo, g_Wobj_lo);
    cudaGetSymbolAddress((void**)&p_Wih_hi,  g_Wih_hi);  cudaGetSymbolAddress((void**)&p_Wih_lo,  g_Wih_lo);
    cudaGetSymbolAddress((void**)&p_Whh_hi,  g_Whh_hi);  cudaGetSymbolAddress((void**)&p_Whh_lo,  g_Whh_lo);
    cudaGetSymbolAddress((void**)&p_WUV_hi,  g_WUV_hi);  cudaGetSymbolAddress((void**)&p_WUV_lo,  g_WUV_lo);
    cudaGetSymbolAddress((void**)&p_WcE_hi,  g_WcE_hi);  cudaGetSymbolAddress((void**)&p_WcE_lo,  g_WcE_lo);
    cudaGetSymbolAddress((void**)&p_Wstk_hi, g_Wstk_hi); cudaGetSymbolAddress((void**)&p_Wstk_lo, g_Wstk_lo);

    const int SMEM_GEMM = 2 * STG_BYTES;   // 49152
    cudaFuncSetAttribute(gemm_mma<1,1>, cudaFuncAttributeMaxDynamicSharedMemorySize, SMEM_GEMM);
    cudaFuncSetAttribute(gemm_mma<0,0>, cudaFuncAttributeMaxDynamicSharedMemorySize, SMEM_GEMM);
    cudaFuncSetAttribute(gemm_mma<0,1>, cudaFuncAttributeMaxDynamicSharedMemorySize, SMEM_GEMM);
    cudaFuncSetAttribute(gemm_mma<0,2>, cudaFuncAttributeMaxDynamicSharedMemorySize, SMEM_GEMM);

    // input + weight splits
    split_f32<<<(ROWS * 128 + 255) / 256, 256>>>(z, p_z_hi, p_z_lo, ROWS * 128);
    split_f32<<<(ROWS * 128 + 255) / 256, 256>>>(h0, p_h0_hi, p_h0_lo, ROWS * 128);
    split_f32<<<(256 * 128 + 255) / 256, 256>>>(W_obj, p_Wobj_hi, p_Wobj_lo, 256 * 128);
    split_f32<<<(384 * 256 + 255) / 256, 256>>>(Wih, p_Wih_hi, p_Wih_lo, 384 * 256);
    split_f32<<<(384 * 128 + 255) / 256, 256>>>(Whh, p_Whh_hi, p_Whh_lo, 384 * 128);
    prep_wuv <<<(1024 * 128 + 255) / 256, 256>>>(We);
    prep_wc  <<<(128 * 640 + 255) / 256, 256>>>(Wc);
    prep_wstk<<<(384 * 128 + 255) / 256, 256>>>(Wl, bl, Wsc, bs, Wh, bh);

    const int MB = ROWS / 128;   // 256

    // G1: z_embed = elu(z @ W_obj^T + b_obj) -> split  [ROWS, 256]
    gemm_mma<1,1><<<dim3(2, MB), 256, SMEM_GEMM>>>(
        p_z_hi, p_z_lo, 128, 128, nullptr, nullptr, 0,
        p_Wobj_hi, p_Wobj_lo, b_obj, nullptr, p_ze_hi, p_ze_lo, 256, nullptr, 128);
    // G2a: gi = z_embed @ Wih^T + bih  [ROWS, 384] f32
    gemm_mma<0,0><<<dim3(3, MB), 256, SMEM_GEMM>>>(
        p_ze_hi, p_ze_lo, 256, 256, nullptr, nullptr, 0,
        p_Wih_hi, p_Wih_lo, bih, p_gi, nullptr, nullptr, 384, nullptr, 256);
    // G2b: gh = h0 @ Whh^T + bhh  [ROWS, 384] f32
    gemm_mma<0,0><<<dim3(3, MB), 256, SMEM_GEMM>>>(
        p_h0_hi, p_h0_lo, 128, 128, nullptr, nullptr, 0,
        p_Whh_hi, p_Whh_lo, bhh, p_gh, nullptr, nullptr, 384, nullptr, 128);
    // GRU gates -> h (split)
    gru_gate<<<(ROWS * 128 + 255) / 256, 256>>>(p_gi, p_gh, h0, p_h_hi, p_h_lo);

    // G3: UV = h @ W_UV^T  [ROWS, 1024] f32
    gemm_mma<0,0><<<dim3(8, MB), 256, SMEM_GEMM>>>(
        p_h_hi, p_h_lo, 128, 128, nullptr, nullptr, 0,
        p_WUV_hi, p_WUV_lo, nullptr, p_UV, nullptr, nullptr, 1024, nullptr, 128);

    // pair stage -> E (split) [ROWS, 512]
    size_t psmem = (2 * 16 * 512) * sizeof(float);   // 65536
    cudaFuncSetAttribute(pair_kernel, cudaFuncAttributeMaxDynamicSharedMemorySize, (int)psmem);
    pair_kernel<<<B_SZ, 512, psmem>>>(p_UV, Wa, ba, be, p_E_hi, p_E_lo);

    // G4: rel = [h | E] @ WcE^T + bc -> split  [ROWS, 128], Kd=640
    gemm_mma<0,1><<<dim3(1, MB), 256, SMEM_GEMM>>>(
        p_h_hi, p_h_lo, 128, 128, p_E_hi, p_E_lo, 512,
        p_WcE_hi, p_WcE_lo, bc, nullptr, p_rel_hi, p_rel_lo, 128, nullptr, 640);

    // G5: [loc|scale|h_out] = rel @ Wstk^T + bstk, final f32 split outputs
    gemm_mma<0,2><<<dim3(3, MB), 256, SMEM_GEMM>>>(
        p_rel_hi, p_rel_lo, 128, 128, nullptr, nullptr, 0,
        p_Wstk_hi, p_Wstk_lo, p_bstk, out1, nullptr, nullptr, 0, out2, 128);
}

// round 8
// speedup vs baseline: 1.2096x; 1.2096x over previous
#include <cuda_runtime.h>
#include <cuda_bf16.h>
#include <math.h>
#include <stdint.h>

#define B_SZ   2048
#define K_OBJ  16
#define ROWS   (B_SZ * K_OBJ)      // 32768
#define NPAIR  120

typedef __nv_bfloat16 bf16;

// ---------------- scratch (device globals; no allocation allowed) ----------------
__device__ __align__(16) bf16 g_z_hi  [(size_t)ROWS * 128];
__device__ __align__(16) bf16 g_z_lo  [(size_t)ROWS * 128];
__device__ __align__(16) bf16 g_h0_hi [(size_t)ROWS * 128];
__device__ __align__(16) bf16 g_h0_lo [(size_t)ROWS * 128];
__device__ __align__(16) bf16 g_ze_hi [(size_t)ROWS * 256];
__device__ __align__(16) bf16 g_ze_lo [(size_t)ROWS * 256];
__device__ __align__(16) bf16 g_h_hi  [(size_t)ROWS * 128];
__device__ __align__(16) bf16 g_h_lo  [(size_t)ROWS * 128];
__device__ __align__(16) bf16 g_E_hi  [(size_t)ROWS * 512];
__device__ __align__(16) bf16 g_E_lo  [(size_t)ROWS * 512];
__device__ __align__(16) bf16 g_rel_hi[(size_t)ROWS * 128];
__device__ __align__(16) bf16 g_rel_lo[(size_t)ROWS * 128];
__device__ __align__(16) float g_gi [(size_t)ROWS * 384];
__device__ __align__(16) float g_gh [(size_t)ROWS * 384];
__device__ __align__(16) float g_UV [(size_t)ROWS * 1024];
__device__ __align__(16) bf16 g_Wobj_hi[256 * 128],  g_Wobj_lo[256 * 128];
__device__ __align__(16) bf16 g_Wih_hi [384 * 256],  g_Wih_lo [384 * 256];
__device__ __align__(16) bf16 g_Whh_hi [384 * 128],  g_Whh_lo [384 * 128];
__device__ __align__(16) bf16 g_WUV_hi [1024 * 128], g_WUV_lo [1024 * 128];
__device__ __align__(16) bf16 g_WcE_hi [128 * 640],  g_WcE_lo [128 * 640];
__device__ __align__(16) bf16 g_Wstk_hi[384 * 128],  g_Wstk_lo[384 * 128];
__device__ __align__(16) float g_bstk[384];

// ---------------- helpers ----------------
__device__ __forceinline__ void bf16split(float x, bf16& h, bf16& l) {
    h = __float2bfloat16_rn(x);
    l = __float2bfloat16_rn(x - __bfloat162float(h));
}

__device__ __forceinline__ uint32_t smem_u32(const void* p) {
    uint32_t a;
    asm("{ .reg .u64 t; cvta.to.shared.u64 t, %1; cvt.u32.u64 %0, t; }" : "=r"(a) : "l"(p));
    return a;
}

__device__ __forceinline__ void cp16(uint32_t dst, const void* src) {
    asm volatile("cp.async.ca.shared.global [%0], [%1], 16;" :: "r"(dst), "l"(src) : "memory");
}
#define CP_COMMIT() asm volatile("cp.async.commit_group;" ::: "memory")
#define CP_WAIT(n)  asm volatile("cp.async.wait_group %0;" :: "n"(n) : "memory")

__device__ __forceinline__ void mma16(float* d, const uint32_t* a, const uint32_t* b) {
    asm volatile(
        "mma.sync.aligned.m16n8k16.row.col.f32.bf16.bf16.f32 "
        "{%0,%1,%2,%3}, {%4,%5,%6,%7}, {%8,%9}, {%0,%1,%2,%3};"
        : "+f"(d[0]), "+f"(d[1]), "+f"(d[2]), "+f"(d[3])
        : "r"(a[0]), "r"(a[1]), "r"(a[2]), "r"(a[3]), "r"(b[0]), "r"(b[1]));
}

// ---------------- tensor-core bf16x3 NT GEMM, K-slab 32, 2-stage ----------------
// C[M,N] = act(X @ W^T + bias); X split at k1 between X1/X2; W [N,Kd] row-major bf16 hi/lo.
// CTA tile 128x128. Per slab: 32 K-elems (two k16 fragment passes), 2-stage cp.async ring.
// Rows padded to 20 words (16 data + 4 pad): banks (20r+kw) mod 32 cover all 32 -> conflict-free.
// OUTM: 0 = f32 C; 1 = bf16-split (Chi, Clo); 2 = final f32 (n<256 -> C ld256, else C2 ld128).
#define PADW 20
#define TILE_WORDS 2560    // 128 * PADW
#define STG_WORDS  10240   // 4 tiles * TILE_WORDS
#define TILE_BYTES (TILE_WORDS * 4)
#define STG_BYTES  (STG_WORDS * 4)

template <int ACT, int OUTM>
__global__ void __launch_bounds__(256, 2) gemm_mma(
    const bf16* __restrict__ X1hi, const bf16* __restrict__ X1lo, int ld1, int k1,
    const bf16* __restrict__ X2hi, const bf16* __restrict__ X2lo, int ld2,
    const bf16* __restrict__ Whi, const bf16* __restrict__ Wlo,
    const float* __restrict__ bias,
    float* __restrict__ C, bf16* __restrict__ Chi, bf16* __restrict__ Clo,
    int ldc, float* __restrict__ C2, int Kd)
{
    extern __shared__ uint32_t smw[];
    const uint32_t sb = smem_u32(smw);

    const int tid = threadIdx.x;
    const int lane = tid & 31;
    const int wid = tid >> 5;
    const int warp_m = wid >> 1;
    const int warp_n = wid & 1;
    const int gid = lane >> 2;
    const int tig = lane & 3;
    const int bm = blockIdx.y * 128;
    const int bn = blockIdx.x * 128;

    float acc[2][8][4];
#pragma unroll
    for (int mi = 0; mi < 2; mi++)
#pragma unroll
        for (int nf = 0; nf < 8; nf++)
#pragma unroll
            for (int e = 0; e < 4; e++) acc[mi][nf][e] = 0.f;

    // loader: 8 cp16 per thread per slab (each tile: 128 rows x 4 chunks of 16B)
    const int lrow = tid >> 1;                 // 0..127
    const int lch2 = (tid & 1) * 2;            // chunk pair 0 or 2

    auto load_slab = [&](int k0, int s) {
        const bf16 *ahi, *alo; int xld, xc;
        if (k0 < k1) { ahi = X1hi; alo = X1lo; xld = ld1; xc = k0; }
        else         { ahi = X2hi; alo = X2lo; xld = ld2; xc = k0 - k1; }
        const uint32_t st = sb + s * STG_BYTES;
#pragma unroll
        for (int c = 0; c < 2; c++) {
            int ch = lch2 + c;                 // chunk 0..3
            uint32_t so = (uint32_t)(lrow * PADW + ch * 4) * 4;
            const size_t ga = (size_t)(bm + lrow) * xld + xc + ch * 8;
            const size_t gw = (size_t)(bn + lrow) * Kd + k0 + ch * 8;
            cp16(st + so,                  ahi + ga);
            cp16(st + TILE_BYTES + so,     alo + ga);
            cp16(st + 2 * TILE_BYTES + so, Whi + gw);
            cp16(st + 3 * TILE_BYTES + so, Wlo + gw);
        }
    };

    int s = 0;
    load_slab(0, 0);
    CP_COMMIT();

#pragma unroll 1
    for (int k0 = 0; k0 < Kd; k0 += 32) {
        if (k0 + 32 < Kd) {
            load_slab(k0 + 32, s ^ 1);
            CP_COMMIT();
            CP_WAIT(1);
        } else {
            CP_WAIT(0);
        }
        __syncthreads();

        const uint32_t* sA  = smw + s * STG_WORDS;
        const uint32_t* sAl = sA + TILE_WORDS;
        const uint32_t* sB  = sA + 2 * TILE_WORDS;
        const uint32_t* sBl = sA + 3 * TILE_WORDS;

#pragma unroll
        for (int h = 0; h < 2; h++) {
            const int kb = h * 8 + tig;
            uint32_t ah[2][4], al[2][4];
#pragma unroll
            for (int mi = 0; mi < 2; mi++) {
                int am = (warp_m * 32 + mi * 16 + gid) * PADW;
                ah[mi][0] = sA [am + kb];
                ah[mi][1] = sA [am + 8 * PADW + kb];
                ah[mi][2] = sA [am + kb + 4];
                ah[mi][3] = sA [am + 8 * PADW + kb + 4];
                al[mi][0] = sAl[am + kb];
                al[mi][1] = sAl[am + 8 * PADW + kb];
                al[mi][2] = sAl[am + kb + 4];
                al[mi][3] = sAl[am + 8 * PADW + kb + 4];
            }
            uint32_t bf[8][2];
#pragma unroll
            for (int nf = 0; nf < 8; nf++) {
                int an = (warp_n * 64 + nf * 8 + gid) * PADW;
                bf[nf][0] = sB[an + kb];
                bf[nf][1] = sB[an + kb + 4];
            }
#pragma unroll
            for (int mi = 0; mi < 2; mi++)
#pragma unroll
                for (int nf = 0; nf < 8; nf++) {
                    mma16(acc[mi][nf], ah[mi], bf[nf]);
                    mma16(acc[mi][nf], al[mi], bf[nf]);
                }
#pragma unroll
            for (int nf = 0; nf < 8; nf++) {
                int an = (warp_n * 64 + nf * 8 + gid) * PADW;
                bf[nf][0] = sBl[an + kb];
                bf[nf][1] = sBl[an + kb + 4];
            }
#pragma unroll
            for (int mi = 0; mi < 2; mi++)
#pragma unroll
                for (int nf = 0; nf < 8; nf++)
                    mma16(acc[mi][nf], ah[mi], bf[nf]);
        }
        __syncthreads();
        s ^= 1;
    }

    // ---- epilogue ----
    float* outp = C; int oldc = ldc, ncol0 = bn;
    if (OUTM == 2) {
        if (bn >= 256) { outp = C2; oldc = 128; ncol0 = bn - 256; }
        else           { outp = C;  oldc = 256; ncol0 = bn; }
    }

#pragma unroll
    for (int mi = 0; mi < 2; mi++) {
        int r0 = bm + warp_m * 32 + mi * 16 + gid;
#pragma unroll
        for (int nf = 0; nf < 8; nf++) {
            int cg = bn + warp_n * 64 + nf * 8 + tig * 2;
            int cl = ncol0 + warp_n * 64 + nf * 8 + tig * 2;
            float b0 = 0.f, b1 = 0.f;
            if (bias) { float2 bv = *(const float2*)(bias + cg); b0 = bv.x; b1 = bv.y; }
            float v00 = acc[mi][nf][0] + b0;
            float v01 = acc[mi][nf][1] + b1;
            float v10 = acc[mi][nf][2] + b0;
            float v11 = acc[mi][nf][3] + b1;
            if (ACT == 1) {
                v00 = (v00 > 0.f) ? v00 : expm1f(v00);
                v01 = (v01 > 0.f) ? v01 : expm1f(v01);
                v10 = (v10 > 0.f) ? v10 : expm1f(v10);
                v11 = (v11 > 0.f) ? v11 : expm1f(v11);
            }
            if (OUTM == 1) {
                bf16 h, l;
                __nv_bfloat162 ph0, pl0, ph1, pl1;
                bf16split(v00, h, l); ph0.x = h; pl0.x = l;
                bf16split(v01, h, l); ph0.y = h; pl0.y = l;
                bf16split(v10, h, l); ph1.x = h; pl1.x = l;
                bf16split(v11, h, l); ph1.y = h; pl1.y = l;
                *(__nv_bfloat162*)(Chi + (size_t)r0 * ldc + cl)       = ph0;
                *(__nv_bfloat162*)(Clo + (size_t)r0 * ldc + cl)       = pl0;
                *(__nv_bfloat162*)(Chi + (size_t)(r0 + 8) * ldc + cl) = ph1;
                *(__nv_bfloat162*)(Clo + (size_t)(r0 + 8) * ldc + cl) = pl1;
            } else {
                *(float2*)(outp + (size_t)r0 * oldc + cl)       = make_float2(v00, v01);
                *(float2*)(outp + (size_t)(r0 + 8) * oldc + cl) = make_float2(v10, v11);
            }
        }
    }
}

// ---------------- split / prep kernels ----------------
__global__ void split_f32(const float* __restrict__ src, bf16* __restrict__ hi,
                          bf16* __restrict__ lo, int n) {
    int idx = blockIdx.x * blockDim.x + threadIdx.x;
    if (idx >= n) return;
    bf16 h, l;
    bf16split(src[idx], h, l);
    hi[idx] = h; lo[idx] = l;
}

__global__ void prep_wuv(const float* __restrict__ We) {
    int idx = blockIdx.x * blockDim.x + threadIdx.x;
    if (idx >= 1024 * 128) return;
    int n = idx >> 7, c = idx & 127;
    float v;
    if (n < 512) v = We[n * 512 + c] + We[n * 512 + 128 + c];
    else {
        int nn = n - 512;
        v = We[nn * 512 + 256 + c] + We[nn * 512 + 384 + c];
    }
    bf16 h, l; bf16split(v, h, l);
    g_WUV_hi[idx] = h; g_WUV_lo[idx] = l;
}

__global__ void prep_wc(const float* __restrict__ Wc) {
    int idx = blockIdx.x * blockDim.x + threadIdx.x;
    if (idx >= 128 * 640) return;
    int n = idx / 640, c = idx % 640;
    float v = (c < 128) ? (Wc[n * 768 + c] + Wc[n * 768 + 128 + c])
                        : Wc[n * 768 + 128 + c];
    bf16 h, l; bf16split(v, h, l);
    g_WcE_hi[idx] = h; g_WcE_lo[idx] = l;
}

__global__ void prep_wstk(const float* __restrict__ Wl, const float* __restrict__ bl,
                          const float* __restrict__ Wsc, const float* __restrict__ bs,
                          const float* __restrict__ Wh, const float* __restrict__ bh) {
    int idx = blockIdx.x * blockDim.x + threadIdx.x;
    if (idx < 384 * 128) {
        int n = idx >> 7, c = idx & 127;
        const float* W = (n < 128) ? Wl : ((n < 256) ? Wsc : Wh);
        bf16 h, l; bf16split(W[(n & 127) * 128 + c], h, l);
        g_Wstk_hi[idx] = h; g_Wstk_lo[idx] = l;
    }
    if (idx < 384) {
        const float* bb = (idx < 128) ? bl : ((idx < 256) ? bs : bh);
        g_bstk[idx] = bb[idx & 127];
    }
}

// ---------------- GRU gate fusion (writes split h) ----------------
__device__ __forceinline__ float sigm(float x) { return 1.f / (1.f + expf(-x)); }

__global__ void gru_gate(const float* __restrict__ gi, const float* __restrict__ gh,
                         const float* __restrict__ h0,
                         bf16* __restrict__ hhi, bf16* __restrict__ hlo) {
    int idx = blockIdx.x * blockDim.x + threadIdx.x;
    if (idx >= ROWS * 128) return;
    int m = idx >> 7, c = idx & 127;
    const float* gim = gi + (size_t)m * 384;
    const float* ghm = gh + (size_t)m * 384;
    float r = sigm(gim[c] + ghm[c]);
    float u = sigm(gim[128 + c] + ghm[128 + c]);
    float n = tanhf(gim[256 + c] + r * ghm[256 + c]);
    float v = (1.f - u) * n + u * h0[idx];
    bf16 h, l; bf16split(v, h, l);
    hhi[idx] = h; hlo[idx] = l;
}

// ---------------- pair stage (R5 atomic version, writes split E) ----------------
__global__ void __launch_bounds__(512) pair_kernel(
    const float* __restrict__ UV, const float* __restrict__ Wa,
    const float* __restrict__ ba, const float* __restrict__ be,
    bf16* __restrict__ Ehi, bf16* __restrict__ Elo)
{
    extern __shared__ float smf[];
    float* Ub  = smf;
    float* Vb  = Ub + 16 * 512;
    float* Eb  = Vb + 16 * 512;
    float* was = Eb + 16 * 512;
    float* bes = was + 512;

    const int b = blockIdx.x;
    const int tid = threadIdx.x;

    for (int i = tid; i < 16 * 512; i += 512) {
        int k = i >> 9, t = i & 511;
        const float* row = UV + (size_t)(b * 16 + k) * 1024;
        Ub[i] = row[t];
        Vb[i] = row[512 + t];
        Eb[i] = 0.f;
    }
    was[tid & 511] = Wa[tid & 511];
    bes[tid & 511] = be[tid & 511];
    __syncthreads();

    const float ba0 = ba[0];
    const int wid = tid >> 5, lane = tid & 31;

    for (int p = wid; p < NPAIR; p += 16) {
        int ii = 0, rem = p, span = K_OBJ - 1;
        while (rem >= span) { rem -= span; ii++; span--; }
        int jj = ii + 1 + rem;

        const float* Ui = Ub + ii * 512;
        const float* Vj = Vb + jj * 512;
        float e[16];
        float dot = 0.f;
#pragma unroll
        for (int c = 0; c < 16; c++) {
            int t = lane + 32 * c;
            float x = Ui[t] + Vj[t] + bes[t];
            x = (x > 0.f) ? x : expm1f(x);
            e[c] = x;
            dot += x * was[t];
        }
#pragma unroll
        for (int o = 16; o > 0; o >>= 1) dot += __shfl_xor_sync(0xffffffffu, dot, o);
        float att = 1.f / (1.f + expf(-(dot + ba0)));

        float* Ei = Eb + ii * 512;
        float* Ej = Eb + jj * 512;
#pragma unroll
        for (int c = 0; c < 16; c++) {
            int t = lane + 32 * c;
            float w = att * e[c];
            atomicAdd(Ei + t, w);
            atomicAdd(Ej + t, w);
        }
    }
    __syncthreads();

    bf16* Eh = Ehi + (size_t)b * 16 * 512;
    bf16* El = Elo + (size_t)b * 16 * 512;
    for (int i = tid; i < 16 * 512; i += 512) {
        bf16 h, l; bf16split(Eb[i], h, l);
        Eh[i] = h; El[i] = l;
    }
}

// ---------------- host launcher ----------------
extern "C" void kernel_launch(void* const* d_in, const int* in_sizes, int n_in,
                              void* d_out, int out_size)
{
    const float* z    = (const float*)d_in[0];
    const float* h0   = (const float*)d_in[1];
    const float* W_obj= (const float*)d_in[2];
    const float* b_obj= (const float*)d_in[3];
    const float* Wih  = (const float*)d_in[4];
    const float* bih  = (const float*)d_in[5];
    const float* Whh  = (const float*)d_in[6];
    const float* bhh  = (const float*)d_in[7];
    const float* We   = (const float*)d_in[8];
    const float* be   = (const float*)d_in[9];
    const float* Wa   = (const float*)d_in[10];
    const float* ba   = (const float*)d_in[11];
    const float* Wc   = (const float*)d_in[12];
    const float* bc   = (const float*)d_in[13];
    const float* Wl   = (const float*)d_in[14];
    const float* bl   = (const float*)d_in[15];
    const float* Wsc  = (const float*)d_in[16];
    const float* bs   = (const float*)d_in[17];
    const float* Wh   = (const float*)d_in[18];
    const float* bh   = (const float*)d_in[19];

    float* out1 = (float*)d_out;                 // [ROWS, 256] = concat(loc, scale)
    float* out2 = out1 + (size_t)ROWS * 256;     // [ROWS, 128] = h_out

    bf16 *p_z_hi, *p_z_lo, *p_h0_hi, *p_h0_lo, *p_ze_hi, *p_ze_lo;
    bf16 *p_h_hi, *p_h_lo, *p_E_hi, *p_E_lo, *p_rel_hi, *p_rel_lo;
    float *p_gi, *p_gh, *p_UV, *p_bstk;
    bf16 *p_Wobj_hi, *p_Wobj_lo, *p_Wih_hi, *p_Wih_lo, *p_Whh_hi, *p_Whh_lo;
    bf16 *p_WUV_hi, *p_WUV_lo, *p_WcE_hi, *p_WcE_lo, *p_Wstk_hi, *p_Wstk_lo;

    cudaGetSymbolAddress((void**)&p_z_hi,  g_z_hi);   cudaGetSymbolAddress((void**)&p_z_lo,  g_z_lo);
    cudaGetSymbolAddress((void**)&p_h0_hi, g_h0_hi);  cudaGetSymbolAddress((void**)&p_h0_lo, g_h0_lo);
    cudaGetSymbolAddress((void**)&p_ze_hi, g_ze_hi);  cudaGetSymbolAddress((void**)&p_ze_lo, g_ze_lo);
    cudaGetSymbolAddress((void**)&p_h_hi,  g_h_hi);   cudaGetSymbolAddress((void**)&p_h_lo,  g_h_lo);
    cudaGetSymbolAddress((void**)&p_E_hi,  g_E_hi);   cudaGetSymbolAddress((void**)&p_E_lo,  g_E_lo);
    cudaGetSymbolAddress((void**)&p_rel_hi,g_rel_hi); cudaGetSymbolAddress((void**)&p_rel_lo,g_rel_lo);
    cudaGetSymbolAddress((void**)&p_gi, g_gi);
    cudaGetSymbolAddress((void**)&p_gh, g_gh);
    cudaGetSymbolAddress((void**)&p_UV, g_UV);
    cudaGetSymbolAddress((void**)&p_bstk, g_bstk);
    cudaGetSymbolAddress((void**)&p_Wobj_hi, g_Wobj_hi); cudaGetSymbolAddress((void**)&p_Wobj_lo, g_Wobj_lo);
    cudaGetSymbolAddress((void**)&p_Wih_hi,  g_Wih_hi);  cudaGetSymbolAddress((void**)&p_Wih_lo,  g_Wih_lo);
    cudaGetSymbolAddress((void**)&p_Whh_hi,  g_Whh_hi);  cudaGetSymbolAddress((void**)&p_Whh_lo,  g_Whh_lo);
    cudaGetSymbolAddress((void**)&p_WUV_hi,  g_WUV_hi);  cudaGetSymbolAddress((void**)&p_WUV_lo,  g_WUV_lo);
    cudaGetSymbolAddress((void**)&p_WcE_hi,  g_WcE_hi);  cudaGetSymbolAddress((void**)&p_WcE_lo,  g_WcE_lo);
    cudaGetSymbolAddress((void**)&p_Wstk_hi, g_Wstk_hi); cudaGetSymbolAddress((void**)&p_Wstk_lo, g_Wstk_lo);

    const int SMEM_GEMM = 2 * STG_BYTES;   // 81920
    cudaFuncSetAttribute(gemm_mma<1,1>, cudaFuncAttributeMaxDynamicSharedMemorySize, SMEM_GEMM);
    cudaFuncSetAttribute(gemm_mma<0,0>, cudaFuncAttributeMaxDynamicSharedMemorySize, SMEM_GEMM);
    cudaFuncSetAttribute(gemm_mma<0,1>, cudaFuncAttributeMaxDynamicSharedMemorySize, SMEM_GEMM);
    cudaFuncSetAttribute(gemm_mma<0,2>, cudaFuncAttributeMaxDynamicSharedMemorySize, SMEM_GEMM);

    // input + weight splits
    split_f32<<<(ROWS * 128 + 255) / 256, 256>>>(z, p_z_hi, p_z_lo, ROWS * 128);
    split_f32<<<(ROWS * 128 + 255) / 256, 256>>>(h0, p_h0_hi, p_h0_lo, ROWS * 128);
    split_f32<<<(256 * 128 + 255) / 256, 256>>>(W_obj, p_Wobj_hi, p_Wobj_lo, 256 * 128);
    split_f32<<<(384 * 256 + 255) / 256, 256>>>(Wih, p_Wih_hi, p_Wih_lo, 384 * 256);
    split_f32<<<(384 * 128 + 255) / 256, 256>>>(Whh, p_Whh_hi, p_Whh_lo, 384 * 128);
    prep_wuv <<<(1024 * 128 + 255) / 256, 256>>>(We);
    prep_wc  <<<(128 * 640 + 255) / 256, 256>>>(Wc);
    prep_wstk<<<(384 * 128 + 255) / 256, 256>>>(Wl, bl, Wsc, bs, Wh, bh);

    const int MB = ROWS / 128;   // 256

    // G1: z_embed = elu(z @ W_obj^T + b_obj) -> split  [ROWS, 256]
    gemm_mma<1,1><<<dim3(2, MB), 256, SMEM_GEMM>>>(
        p_z_hi, p_z_lo, 128, 128, nullptr, nullptr, 0,
        p_Wobj_hi, p_Wobj_lo, b_obj, nullptr, p_ze_hi, p_ze_lo, 256, nullptr, 128);
    // G2a: gi = z_embed @ Wih^T + bih  [ROWS, 384] f32
    gemm_mma<0,0><<<dim3(3, MB), 256, SMEM_GEMM>>>(
        p_ze_hi, p_ze_lo, 256, 256, nullptr, nullptr, 0,
        p_Wih_hi, p_Wih_lo, bih, p_gi, nullptr, nullptr, 384, nullptr, 256);
    // G2b: gh = h0 @ Whh^T + bhh  [ROWS, 384] f32
    gemm_mma<0,0><<<dim3(3, MB), 256, SMEM_GEMM>>>(
        p_h0_hi, p_h0_lo, 128, 128, nullptr, nullptr, 0,
        p_Whh_hi, p_Whh_lo, bhh, p_gh, nullptr, nullptr, 384, nullptr, 128);
    // GRU gates -> h (split)
    gru_gate<<<(ROWS * 128 + 255) / 256, 256>>>(p_gi, p_gh, h0, p_h_hi, p_h_lo);

    // G3: UV = h @ W_UV^T  [ROWS, 1024] f32
    gemm_mma<0,0><<<dim3(8, MB), 256, SMEM_GEMM>>>(
        p_h_hi, p_h_lo, 128, 128, nullptr, nullptr, 0,
        p_WUV_hi, p_WUV_lo, nullptr, p_UV, nullptr, nullptr, 1024, nullptr, 128);

    // pair stage -> E (split) [ROWS, 512]
    size_t psmem = (3 * 16 * 512 + 1024) * sizeof(float);
    cudaFuncSetAttribute(pair_kernel, cudaFuncAttributeMaxDynamicSharedMemorySize, (int)psmem);
    pair_kernel<<<B_SZ, 512, psmem>>>(p_UV, Wa, ba, be, p_E_hi, p_E_lo);

    // G4: rel = [h | E] @ WcE^T + bc -> split  [ROWS, 128], Kd=640
    gemm_mma<0,1><<<dim3(1, MB), 256, SMEM_GEMM>>>(
        p_h_hi, p_h_lo, 128, 128, p_E_hi, p_E_lo, 512,
        p_WcE_hi, p_WcE_lo, bc, nullptr, p_rel_hi, p_rel_lo, 128, nullptr, 640);

    // G5: [loc|scale|h_out] = rel @ Wstk^T + bstk, final f32 split outputs
    gemm_mma<0,2><<<dim3(3, MB), 256, SMEM_GEMM>>>(
        p_rel_hi, p_rel_lo, 128, 128, nullptr, nullptr, 0,
        p_Wstk_hi, p_Wstk_lo, p_bstk, out1, nullptr, nullptr, 0, out2, 128);
}

// round 9
// speedup vs baseline: 1.2990x; 1.0740x over previous
#include <cuda_runtime.h>
#include <cuda_bf16.h>
#include <math.h>
#include <stdint.h>

#define B_SZ   2048
#define K_OBJ  16
#define ROWS   (B_SZ * K_OBJ)      // 32768
#define NPAIR  120

typedef __nv_bfloat16 bf16;

// ---------------- scratch (device globals; no allocation allowed) ----------------
__device__ __align__(16) bf16 g_z_hi  [(size_t)ROWS * 128];
__device__ __align__(16) bf16 g_z_lo  [(size_t)ROWS * 128];
__device__ __align__(16) bf16 g_h0_hi [(size_t)ROWS * 128];
__device__ __align__(16) bf16 g_h0_lo [(size_t)ROWS * 128];
__device__ __align__(16) bf16 g_ze_hi [(size_t)ROWS * 256];
__device__ __align__(16) bf16 g_ze_lo [(size_t)ROWS * 256];
__device__ __align__(16) bf16 g_h_hi  [(size_t)ROWS * 128];
__device__ __align__(16) bf16 g_h_lo  [(size_t)ROWS * 128];
__device__ __align__(16) bf16 g_E_hi  [(size_t)ROWS * 512];
__device__ __align__(16) bf16 g_E_lo  [(size_t)ROWS * 512];
__device__ __align__(16) bf16 g_rel_hi[(size_t)ROWS * 128];
__device__ __align__(16) bf16 g_rel_lo[(size_t)ROWS * 128];
__device__ __align__(16) float g_gi [(size_t)ROWS * 384];
__device__ __align__(16) float g_gh [(size_t)ROWS * 384];
__device__ __align__(16) float g_UV [(size_t)ROWS * 1024];
__device__ __align__(16) bf16 g_Wobj_hi[256 * 128],  g_Wobj_lo[256 * 128];
__device__ __align__(16) bf16 g_Wih_hi [384 * 256],  g_Wih_lo [384 * 256];
__device__ __align__(16) bf16 g_Whh_hi [384 * 128],  g_Whh_lo [384 * 128];
__device__ __align__(16) bf16 g_WUV_hi [1024 * 128], g_WUV_lo [1024 * 128];
__device__ __align__(16) bf16 g_WcE_hi [128 * 640],  g_WcE_lo [128 * 640];
__device__ __align__(16) bf16 g_Wstk_hi[384 * 128],  g_Wstk_lo[384 * 128];
__device__ __align__(16) float g_bstk[384];

// ---------------- helpers ----------------
__device__ __forceinline__ void bf16split(float x, bf16& h, bf16& l) {
    h = __float2bfloat16_rn(x);
    l = __float2bfloat16_rn(x - __bfloat162float(h));
}

__device__ __forceinline__ uint32_t smem_u32(const void* p) {
    uint32_t a;
    asm("{ .reg .u64 t; cvta.to.shared.u64 t, %1; cvt.u32.u64 %0, t; }" : "=r"(a) : "l"(p));
    return a;
}

__device__ __forceinline__ void cp16(uint32_t dst, const void* src) {
    asm volatile("cp.async.ca.shared.global [%0], [%1], 16;" :: "r"(dst), "l"(src) : "memory");
}
#define CP_COMMIT() asm volatile("cp.async.commit_group;" ::: "memory")
#define CP_WAIT(n)  asm volatile("cp.async.wait_group %0;" :: "n"(n) : "memory")

__device__ __forceinline__ void mma16(float* d, const uint32_t* a, const uint32_t* b) {
    asm volatile(
        "mma.sync.aligned.m16n8k16.row.col.f32.bf16.bf16.f32 "
        "{%0,%1,%2,%3}, {%4,%5,%6,%7}, {%8,%9}, {%0,%1,%2,%3};"
        : "+f"(d[0]), "+f"(d[1]), "+f"(d[2]), "+f"(d[3])
        : "r"(a[0]), "r"(a[1]), "r"(a[2]), "r"(a[3]), "r"(b[0]), "r"(b[1]));
}

// ---------------- tensor-core bf16x3 NT GEMM, K-slab 32, 2-stage (R8) ----------------
#define PADW 20
#define TILE_WORDS 2560    // 128 * PADW
#define STG_WORDS  10240   // 4 tiles * TILE_WORDS
#define TILE_BYTES (TILE_WORDS * 4)
#define STG_BYTES  (STG_WORDS * 4)

template <int ACT, int OUTM>
__global__ void __launch_bounds__(256, 2) gemm_mma(
    const bf16* __restrict__ X1hi, const bf16* __restrict__ X1lo, int ld1, int k1,
    const bf16* __restrict__ X2hi, const bf16* __restrict__ X2lo, int ld2,
    const bf16* __restrict__ Whi, const bf16* __restrict__ Wlo,
    const float* __restrict__ bias,
    float* __restrict__ C, bf16* __restrict__ Chi, bf16* __restrict__ Clo,
    int ldc, float* __restrict__ C2, int Kd)
{
    extern __shared__ uint32_t smw[];
    const uint32_t sb = smem_u32(smw);

    const int tid = threadIdx.x;
    const int lane = tid & 31;
    const int wid = tid >> 5;
    const int warp_m = wid >> 1;
    const int warp_n = wid & 1;
    const int gid = lane >> 2;
    const int tig = lane & 3;
    const int bm = blockIdx.y * 128;
    const int bn = blockIdx.x * 128;

    float acc[2][8][4];
#pragma unroll
    for (int mi = 0; mi < 2; mi++)
#pragma unroll
        for (int nf = 0; nf < 8; nf++)
#pragma unroll
            for (int e = 0; e < 4; e++) acc[mi][nf][e] = 0.f;

    const int lrow = tid >> 1;
    const int lch2 = (tid & 1) * 2;

    auto load_slab = [&](int k0, int s) {
        const bf16 *ahi, *alo; int xld, xc;
        if (k0 < k1) { ahi = X1hi; alo = X1lo; xld = ld1; xc = k0; }
        else         { ahi = X2hi; alo = X2lo; xld = ld2; xc = k0 - k1; }
        const uint32_t st = sb + s * STG_BYTES;
#pragma unroll
        for (int c = 0; c < 2; c++) {
            int ch = lch2 + c;
            uint32_t so = (uint32_t)(lrow * PADW + ch * 4) * 4;
            const size_t ga = (size_t)(bm + lrow) * xld + xc + ch * 8;
            const size_t gw = (size_t)(bn + lrow) * Kd + k0 + ch * 8;
            cp16(st + so,                  ahi + ga);
            cp16(st + TILE_BYTES + so,     alo + ga);
            cp16(st + 2 * TILE_BYTES + so, Whi + gw);
            cp16(st + 3 * TILE_BYTES + so, Wlo + gw);
        }
    };

    int s = 0;
    load_slab(0, 0);
    CP_COMMIT();

#pragma unroll 1
    for (int k0 = 0; k0 < Kd; k0 += 32) {
        if (k0 + 32 < Kd) {
            load_slab(k0 + 32, s ^ 1);
            CP_COMMIT();
            CP_WAIT(1);
        } else {
            CP_WAIT(0);
        }
        __syncthreads();

        const uint32_t* sA  = smw + s * STG_WORDS;
        const uint32_t* sAl = sA + TILE_WORDS;
        const uint32_t* sB  = sA + 2 * TILE_WORDS;
        const uint32_t* sBl = sA + 3 * TILE_WORDS;

#pragma unroll
        for (int h = 0; h < 2; h++) {
            const int kb = h * 8 + tig;
            uint32_t ah[2][4], al[2][4];
#pragma unroll
            for (int mi = 0; mi < 2; mi++) {
                int am = (warp_m * 32 + mi * 16 + gid) * PADW;
                ah[mi][0] = sA [am + kb];
                ah[mi][1] = sA [am + 8 * PADW + kb];
                ah[mi][2] = sA [am + kb + 4];
                ah[mi][3] = sA [am + 8 * PADW + kb + 4];
                al[mi][0] = sAl[am + kb];
                al[mi][1] = sAl[am + 8 * PADW + kb];
                al[mi][2] = sAl[am + kb + 4];
                al[mi][3] = sAl[am + 8 * PADW + kb + 4];
            }
            uint32_t bf[8][2];
#pragma unroll
            for (int nf = 0; nf < 8; nf++) {
                int an = (warp_n * 64 + nf * 8 + gid) * PADW;
                bf[nf][0] = sB[an + kb];
                bf[nf][1] = sB[an + kb + 4];
            }
#pragma unroll
            for (int mi = 0; mi < 2; mi++)
#pragma unroll
                for (int nf = 0; nf < 8; nf++) {
                    mma16(acc[mi][nf], ah[mi], bf[nf]);
                    mma16(acc[mi][nf], al[mi], bf[nf]);
                }
#pragma unroll
            for (int nf = 0; nf < 8; nf++) {
                int an = (warp_n * 64 + nf * 8 + gid) * PADW;
                bf[nf][0] = sBl[an + kb];
                bf[nf][1] = sBl[an + kb + 4];
            }
#pragma unroll
            for (int mi = 0; mi < 2; mi++)
#pragma unroll
                for (int nf = 0; nf < 8; nf++)
                    mma16(acc[mi][nf], ah[mi], bf[nf]);
        }
        __syncthreads();
        s ^= 1;
    }

    // ---- epilogue ----
    float* outp = C; int oldc = ldc, ncol0 = bn;
    if (OUTM == 2) {
        if (bn >= 256) { outp = C2; oldc = 128; ncol0 = bn - 256; }
        else           { outp = C;  oldc = 256; ncol0 = bn; }
    }

#pragma unroll
    for (int mi = 0; mi < 2; mi++) {
        int r0 = bm + warp_m * 32 + mi * 16 + gid;
#pragma unroll
        for (int nf = 0; nf < 8; nf++) {
            int cg = bn + warp_n * 64 + nf * 8 + tig * 2;
            int cl = ncol0 + warp_n * 64 + nf * 8 + tig * 2;
            float b0 = 0.f, b1 = 0.f;
            if (bias) { float2 bv = *(const float2*)(bias + cg); b0 = bv.x; b1 = bv.y; }
            float v00 = acc[mi][nf][0] + b0;
            float v01 = acc[mi][nf][1] + b1;
            float v10 = acc[mi][nf][2] + b0;
            float v11 = acc[mi][nf][3] + b1;
            if (ACT == 1) {
                v00 = (v00 > 0.f) ? v00 : (__expf(v00) - 1.f);
                v01 = (v01 > 0.f) ? v01 : (__expf(v01) - 1.f);
                v10 = (v10 > 0.f) ? v10 : (__expf(v10) - 1.f);
                v11 = (v11 > 0.f) ? v11 : (__expf(v11) - 1.f);
            }
            if (OUTM == 1) {
                bf16 h, l;
                __nv_bfloat162 ph0, pl0, ph1, pl1;
                bf16split(v00, h, l); ph0.x = h; pl0.x = l;
                bf16split(v01, h, l); ph0.y = h; pl0.y = l;
                bf16split(v10, h, l); ph1.x = h; pl1.x = l;
                bf16split(v11, h, l); ph1.y = h; pl1.y = l;
                *(__nv_bfloat162*)(Chi + (size_t)r0 * ldc + cl)       = ph0;
                *(__nv_bfloat162*)(Clo + (size_t)r0 * ldc + cl)       = pl0;
                *(__nv_bfloat162*)(Chi + (size_t)(r0 + 8) * ldc + cl) = ph1;
                *(__nv_bfloat162*)(Clo + (size_t)(r0 + 8) * ldc + cl) = pl1;
            } else {
                *(float2*)(outp + (size_t)r0 * oldc + cl)       = make_float2(v00, v01);
                *(float2*)(outp + (size_t)(r0 + 8) * oldc + cl) = make_float2(v10, v11);
            }
        }
    }
}

// ---------------- split / prep kernels ----------------
__global__ void split_f32(const float* __restrict__ src, bf16* __restrict__ hi,
                          bf16* __restrict__ lo, int n) {
    int idx = blockIdx.x * blockDim.x + threadIdx.x;
    if (idx >= n) return;
    bf16 h, l;
    bf16split(src[idx], h, l);
    hi[idx] = h; lo[idx] = l;
}

__global__ void prep_wuv(const float* __restrict__ We) {
    int idx = blockIdx.x * blockDim.x + threadIdx.x;
    if (idx >= 1024 * 128) return;
    int n = idx >> 7, c = idx & 127;
    float v;
    if (n < 512) v = We[n * 512 + c] + We[n * 512 + 128 + c];
    else {
        int nn = n - 512;
        v = We[nn * 512 + 256 + c] + We[nn * 512 + 384 + c];
    }
    bf16 h, l; bf16split(v, h, l);
    g_WUV_hi[idx] = h; g_WUV_lo[idx] = l;
}

__global__ void prep_wc(const float* __restrict__ Wc) {
    int idx = blockIdx.x * blockDim.x + threadIdx.x;
    if (idx >= 128 * 640) return;
    int n = idx / 640, c = idx % 640;
    float v = (c < 128) ? (Wc[n * 768 + c] + Wc[n * 768 + 128 + c])
                        : Wc[n * 768 + 128 + c];
    bf16 h, l; bf16split(v, h, l);
    g_WcE_hi[idx] = h; g_WcE_lo[idx] = l;
}

__global__ void prep_wstk(const float* __restrict__ Wl, const float* __restrict__ bl,
                          const float* __restrict__ Wsc, const float* __restrict__ bs,
                          const float* __restrict__ Wh, const float* __restrict__ bh) {
    int idx = blockIdx.x * blockDim.x + threadIdx.x;
    if (idx < 384 * 128) {
        int n = idx >> 7, c = idx & 127;
        const float* W = (n < 128) ? Wl : ((n < 256) ? Wsc : Wh);
        bf16 h, l; bf16split(W[(n & 127) * 128 + c], h, l);
        g_Wstk_hi[idx] = h; g_Wstk_lo[idx] = l;
    }
    if (idx < 384) {
        const float* bb = (idx < 128) ? bl : ((idx < 256) ? bs : bh);
        g_bstk[idx] = bb[idx & 127];
    }
}

// ---------------- GRU gate fusion (writes split h) ----------------
__device__ __forceinline__ float sigm(float x) { return 1.f / (1.f + __expf(-x)); }

__global__ void gru_gate(const float* __restrict__ gi, const float* __restrict__ gh,
                         const float* __restrict__ h0,
                         bf16* __restrict__ hhi, bf16* __restrict__ hlo) {
    int idx = blockIdx.x * blockDim.x + threadIdx.x;
    if (idx >= ROWS * 128) return;
    int m = idx >> 7, c = idx & 127;
    const float* gim = gi + (size_t)m * 384;
    const float* ghm = gh + (size_t)m * 384;
    float r = sigm(gim[c] + ghm[c]);
    float u = sigm(gim[128 + c] + ghm[128 + c]);
    float n = tanhf(gim[256 + c] + r * ghm[256 + c]);
    float v = (1.f - u) * n + u * h0[idx];
    bf16 h, l; bf16split(v, h, l);
    hhi[idx] = h; hlo[idx] = l;
}

// ---------------- pair stage: warp-per-object, atomic-free (R7, fast exp) ----------------
__global__ void __launch_bounds__(512) pair_kernel(
    const float* __restrict__ UV, const float* __restrict__ Wa,
    const float* __restrict__ ba, const float* __restrict__ be,
    bf16* __restrict__ Ehi, bf16* __restrict__ Elo)
{
    extern __shared__ float smf[];
    float* Ub = smf;                 // 16*512
    float* Vb = Ub + 16 * 512;       // 16*512

    const int b = blockIdx.x;
    const int tid = threadIdx.x;
    const int w = tid >> 5, lane = tid & 31;

    for (int i = tid; i < 16 * 512; i += 512) {
        int k = i >> 9, t = i & 511;
        const float* row = UV + (size_t)(b * 16 + k) * 1024;
        Ub[i] = row[t];
        Vb[i] = row[512 + t];
    }
    __syncthreads();

    const float ba0 = __ldg(&ba[0]);
    float uw[16], vw[16], ber[16], war[16], Ew[16];
#pragma unroll
    for (int c = 0; c < 16; c++) {
        int t = lane + 32 * c;
        uw[c] = Ub[w * 512 + t];
        vw[c] = Vb[w * 512 + t];
        ber[c] = __ldg(&be[t]);
        war[c] = __ldg(&Wa[t]);
        Ew[c] = 0.f;
    }

#pragma unroll 1
    for (int o = 0; o < K_OBJ; o++) {
        if (o == w) continue;
        const float* Urow = Ub + o * 512;
        const float* Vrow = Vb + o * 512;
        float e[16];
        float dot = 0.f;
        if (o > w) {
#pragma unroll
            for (int c = 0; c < 16; c++) {
                float x = uw[c] + Vrow[lane + 32 * c] + ber[c];
                x = (x > 0.f) ? x : (__expf(x) - 1.f);
                e[c] = x;
                dot += x * war[c];
            }
        } else {
#pragma unroll
            for (int c = 0; c < 16; c++) {
                float x = Urow[lane + 32 * c] + vw[c] + ber[c];
                x = (x > 0.f) ? x : (__expf(x) - 1.f);
                e[c] = x;
                dot += x * war[c];
            }
        }
#pragma unroll
        for (int off = 16; off > 0; off >>= 1) dot += __shfl_xor_sync(0xffffffffu, dot, off);
        float att = 1.f / (1.f + __expf(-(dot + ba0)));
#pragma unroll
        for (int c = 0; c < 16; c++) Ew[c] += att * e[c];
    }

    bf16* Eh = Ehi + ((size_t)b * 16 + w) * 512;
    bf16* El = Elo + ((size_t)b * 16 + w) * 512;
#pragma unroll
    for (int c = 0; c < 16; c++) {
        bf16 h, l; bf16split(Ew[c], h, l);
        Eh[lane + 32 * c] = h;
        El[lane + 32 * c] = l;
    }
}

// ---------------- host launcher ----------------
extern "C" void kernel_launch(void* const* d_in, const int* in_sizes, int n_in,
                              void* d_out, int out_size)
{
    const float* z    = (const float*)d_in[0];
    const float* h0   = (const float*)d_in[1];
    const float* W_obj= (const float*)d_in[2];
    const float* b_obj= (const float*)d_in[3];
    const float* Wih  = (const float*)d_in[4];
    const float* bih  = (const float*)d_in[5];
    const float* Whh  = (const float*)d_in[6];
    const float* bhh  = (const float*)d_in[7];
    const float* We   = (const float*)d_in[8];
    const float* be   = (const float*)d_in[9];
    const float* Wa   = (const float*)d_in[10];
    const float* ba   = (const float*)d_in[11];
    const float* Wc   = (const float*)d_in[12];
    const float* bc   = (const float*)d_in[13];
    const float* Wl   = (const float*)d_in[14];
    const float* bl   = (const float*)d_in[15];
    const float* Wsc  = (const float*)d_in[16];
    const float* bs   = (const float*)d_in[17];
    const float* Wh   = (const float*)d_in[18];
    const float* bh   = (const float*)d_in[19];

    float* out1 = (float*)d_out;                 // [ROWS, 256] = concat(loc, scale)
    float* out2 = out1 + (size_t)ROWS * 256;     // [ROWS, 128] = h_out

    bf16 *p_z_hi, *p_z_lo, *p_h0_hi, *p_h0_lo, *p_ze_hi, *p_ze_lo;
    bf16 *p_h_hi, *p_h_lo, *p_E_hi, *p_E_lo, *p_rel_hi, *p_rel_lo;
    float *p_gi, *p_gh, *p_UV, *p_bstk;
    bf16 *p_Wobj_hi, *p_Wobj_lo, *p_Wih_hi, *p_Wih_lo, *p_Whh_hi, *p_Whh_lo;
    bf16 *p_WUV_hi, *p_WUV_lo, *p_WcE_hi, *p_WcE_lo, *p_Wstk_hi, *p_Wstk_lo;

    cudaGetSymbolAddress((void**)&p_z_hi,  g_z_hi);   cudaGetSymbolAddress((void**)&p_z_lo,  g_z_lo);
    cudaGetSymbolAddress((void**)&p_h0_hi, g_h0_hi);  cudaGetSymbolAddress((void**)&p_h0_lo, g_h0_lo);
    cudaGetSymbolAddress((void**)&p_ze_hi, g_ze_hi);  cudaGetSymbolAddress((void**)&p_ze_lo, g_ze_lo);
    cudaGetSymbolAddress((void**)&p_h_hi,  g_h_hi);   cudaGetSymbolAddress((void**)&p_h_lo,  g_h_lo);
    cudaGetSymbolAddress((void**)&p_E_hi,  g_E_hi);   cudaGetSymbolAddress((void**)&p_E_lo,  g_E_lo);
    cudaGetSymbolAddress((void**)&p_rel_hi,g_rel_hi); cudaGetSymbolAddress((void**)&p_rel_lo,g_rel_lo);
    cudaGetSymbolAddress((void**)&p_gi, g_gi);
    cudaGetSymbolAddress((void**)&p_gh, g_gh);
    cudaGetSymbolAddress((void**)&p_UV, g_UV);
    cudaGetSymbolAddress((void**)&p_bstk, g_bstk);
    cudaGetSymbolAddress((void**)&p_Wobj_hi, g_Wobj_hi); cudaGetSymbolAddress((void**)&p_Wobj_lo, g_Wobj_lo);
    cudaGetSymbolAddress((void**)&p_Wih_hi,  g_Wih_hi);  cudaGetSymbolAddress((void**)&p_Wih_lo,  g_Wih_lo);
    cudaGetSymbolAddress((void**)&p_Whh_hi,  g_Whh_hi);  cudaGetSymbolAddress((void**)&p_Whh_lo,  g_Whh_lo);
    cudaGetSymbolAddress((void**)&p_WUV_hi,  g_WUV_hi);  cudaGetSymbolAddress((void**)&p_WUV_lo,  g_WUV_lo);
    cudaGetSymbolAddress((void**)&p_WcE_hi,  g_WcE_hi);  cudaGetSymbolAddress((void**)&p_WcE_lo,  g_WcE_lo);
    cudaGetSymbolAddress((void**)&p_Wstk_hi, g_Wstk_hi); cudaGetSymbolAddress((void**)&p_Wstk_lo, g_Wstk_lo);

    const int SMEM_GEMM = 2 * STG_BYTES;   // 81920
    cudaFuncSetAttribute(gemm_mma<1,1>, cudaFuncAttributeMaxDynamicSharedMemorySize, SMEM_GEMM);
    cudaFuncSetAttribute(gemm_mma<0,0>, cudaFuncAttributeMaxDynamicSharedMemorySize, SMEM_GEMM);
    cudaFuncSetAttribute(gemm_mma<0,1>, cudaFuncAttributeMaxDynamicSharedMemorySize, SMEM_GEMM);
    cudaFuncSetAttribute(gemm_mma<0,2>, cudaFuncAttributeMaxDynamicSharedMemorySize, SMEM_GEMM);

    // input + weight splits
    split_f32<<<(ROWS * 128 + 255) / 256, 256>>>(z, p_z_hi, p_z_lo, ROWS * 128);
    split_f32<<<(ROWS * 128 + 255) / 256, 256>>>(h0, p_h0_hi, p_h0_lo, ROWS * 128);
    split_f32<<<(256 * 128 + 255) / 256, 256>>>(W_obj, p_Wobj_hi, p_Wobj_lo, 256 * 128);
    split_f32<<<(384 * 256 + 255) / 256, 256>>>(Wih, p_Wih_hi, p_Wih_lo, 384 * 256);
    split_f32<<<(384 * 128 + 255) / 256, 256>>>(Whh, p_Whh_hi, p_Whh_lo, 384 * 128);
    prep_wuv <<<(1024 * 128 + 255) / 256, 256>>>(We);
    prep_wc  <<<(128 * 640 + 255) / 256, 256>>>(Wc);
    prep_wstk<<<(384 * 128 + 255) / 256, 256>>>(Wl, bl, Wsc, bs, Wh, bh);

    const int MB = ROWS / 128;   // 256

    // G1: z_embed = elu(z @ W_obj^T + b_obj) -> split  [ROWS, 256]
    gemm_mma<1,1><<<dim3(2, MB), 256, SMEM_GEMM>>>(
        p_z_hi, p_z_lo, 128, 128, nullptr, nullptr, 0,
        p_Wobj_hi, p_Wobj_lo, b_obj, nullptr, p_ze_hi, p_ze_lo, 256, nullptr, 128);
    // G2a: gi = z_embed @ Wih^T + bih  [ROWS, 384] f32
    gemm_mma<0,0><<<dim3(3, MB), 256, SMEM_GEMM>>>(
        p_ze_hi, p_ze_lo, 256, 256, nullptr, nullptr, 0,
        p_Wih_hi, p_Wih_lo, bih, p_gi, nullptr, nullptr, 384, nullptr, 256);
    // G2b: gh = h0 @ Whh^T + bhh  [ROWS, 384] f32
    gemm_mma<0,0><<<dim3(3, MB), 256, SMEM_GEMM>>>(
        p_h0_hi, p_h0_lo, 128, 128, nullptr, nullptr, 0,
        p_Whh_hi, p_Whh_lo, bhh, p_gh, nullptr, nullptr, 384, nullptr, 128);
    // GRU gates -> h (split)
    gru_gate<<<(ROWS * 128 + 255) / 256, 256>>>(p_gi, p_gh, h0, p_h_hi, p_h_lo);

    // G3: UV = h @ W_UV^T  [ROWS, 1024] f32
    gemm_mma<0,0><<<dim3(8, MB), 256, SMEM_GEMM>>>(
        p_h_hi, p_h_lo, 128, 128, nullptr, nullptr, 0,
        p_WUV_hi, p_WUV_lo, nullptr, p_UV, nullptr, nullptr, 1024, nullptr, 128);

    // pair stage -> E (split) [ROWS, 512], atomic-free
    size_t psmem = (2 * 16 * 512) * sizeof(float);   // 65536
    cudaFuncSetAttribute(pair_kernel, cudaFuncAttributeMaxDynamicSharedMemorySize, (int)psmem);
    pair_kernel<<<B_SZ, 512, psmem>>>(p_UV, Wa, ba, be, p_E_hi, p_E_lo);

    // G4: rel = [h | E] @ WcE^T + bc -> split  [ROWS, 128], Kd=640
    gemm_mma<0,1><<<dim3(1, MB), 256, SMEM_GEMM>>>(
        p_h_hi, p_h_lo, 128, 128, p_E_hi, p_E_lo, 512,
        p_WcE_hi, p_WcE_lo, bc, nullptr, p_rel_hi, p_rel_lo, 128, nullptr, 640);

    // G5: [loc|scale|h_out] = rel @ Wstk^T + bstk, final f32 split outputs
    gemm_mma<0,2><<<dim3(3, MB), 256, SMEM_GEMM>>>(
        p_rel_hi, p_rel_lo, 128, 128, nullptr, nullptr, 0,
        p_Wstk_hi, p_Wstk_lo, p_bstk, out1, nullptr, nullptr, 0, out2, 128);
}

// round 10
// speedup vs baseline: 1.3208x; 1.0168x over previous
#include <cuda_runtime.h>
#include <cuda_bf16.h>
#include <math.h>
#include <stdint.h>

#define B_SZ   2048
#define K_OBJ  16
#define ROWS   (B_SZ * K_OBJ)      // 32768
#define NPAIR  120

typedef __nv_bfloat16 bf16;

// ---------------- scratch (device globals; no allocation allowed) ----------------
__device__ __align__(16) bf16 g_z_hi  [(size_t)ROWS * 128];
__device__ __align__(16) bf16 g_z_lo  [(size_t)ROWS * 128];
__device__ __align__(16) bf16 g_h0_hi [(size_t)ROWS * 128];
__device__ __align__(16) bf16 g_h0_lo [(size_t)ROWS * 128];
__device__ __align__(16) bf16 g_ze_hi [(size_t)ROWS * 256];
__device__ __align__(16) bf16 g_ze_lo [(size_t)ROWS * 256];
__device__ __align__(16) bf16 g_h_hi  [(size_t)ROWS * 128];
__device__ __align__(16) bf16 g_h_lo  [(size_t)ROWS * 128];
__device__ __align__(16) bf16 g_E_hi  [(size_t)ROWS * 512];
__device__ __align__(16) bf16 g_E_lo  [(size_t)ROWS * 512];
__device__ __align__(16) bf16 g_rel_hi[(size_t)ROWS * 128];
__device__ __align__(16) bf16 g_rel_lo[(size_t)ROWS * 128];
__device__ __align__(16) float g_gi [(size_t)ROWS * 384];
__device__ __align__(16) float g_gh [(size_t)ROWS * 384];
__device__ __align__(16) float g_UV [(size_t)ROWS * 1024];
__device__ __align__(16) bf16 g_Wobj_hi[256 * 128],  g_Wobj_lo[256 * 128];
__device__ __align__(16) bf16 g_Wih_hi [384 * 256],  g_Wih_lo [384 * 256];
__device__ __align__(16) bf16 g_Whh_hi [384 * 128],  g_Whh_lo [384 * 128];
__device__ __align__(16) bf16 g_WUV_hi [1024 * 128], g_WUV_lo [1024 * 128];
__device__ __align__(16) bf16 g_WcE_hi [128 * 640],  g_WcE_lo [128 * 640];
__device__ __align__(16) bf16 g_Wstk_hi[384 * 128],  g_Wstk_lo[384 * 128];
__device__ __align__(16) float g_bstk[384];

// ---------------- helpers ----------------
__device__ __forceinline__ void bf16split(float x, bf16& h, bf16& l) {
    h = __float2bfloat16_rn(x);
    l = __float2bfloat16_rn(x - __bfloat162float(h));
}

__device__ __forceinline__ uint32_t smem_u32(const void* p) {
    uint32_t a;
    asm("{ .reg .u64 t; cvta.to.shared.u64 t, %1; cvt.u32.u64 %0, t; }" : "=r"(a) : "l"(p));
    return a;
}

__device__ __forceinline__ void cp16(uint32_t dst, const void* src) {
    asm volatile("cp.async.ca.shared.global [%0], [%1], 16;" :: "r"(dst), "l"(src) : "memory");
}
#define CP_COMMIT() asm volatile("cp.async.commit_group;" ::: "memory")
#define CP_WAIT(n)  asm volatile("cp.async.wait_group %0;" :: "n"(n) : "memory")

__device__ __forceinline__ void mma16(float* d, const uint32_t* a, const uint32_t* b) {
    asm volatile(
        "mma.sync.aligned.m16n8k16.row.col.f32.bf16.bf16.f32 "
        "{%0,%1,%2,%3}, {%4,%5,%6,%7}, {%8,%9}, {%0,%1,%2,%3};"
        : "+f"(d[0]), "+f"(d[1]), "+f"(d[2]), "+f"(d[3])
        : "r"(a[0]), "r"(a[1]), "r"(a[2]), "r"(a[3]), "r"(b[0]), "r"(b[1]));
}

// ---------------- tensor-core bf16x3 NT GEMM, K-slab 32, 2-stage ----------------
// MMA issue order: full hh sweep (16 independent acc), then lh sweep, then hl sweep.
// Adjacent same-acc MMAs are 16 instructions apart -> RAW latency hidden.
#define PADW 20
#define TILE_WORDS 2560    // 128 * PADW
#define STG_WORDS  10240   // 4 tiles * TILE_WORDS
#define TILE_BYTES (TILE_WORDS * 4)
#define STG_BYTES  (STG_WORDS * 4)

template <int ACT, int OUTM>
__global__ void __launch_bounds__(256, 2) gemm_mma(
    const bf16* __restrict__ X1hi, const bf16* __restrict__ X1lo, int ld1, int k1,
    const bf16* __restrict__ X2hi, const bf16* __restrict__ X2lo, int ld2,
    const bf16* __restrict__ Whi, const bf16* __restrict__ Wlo,
    const float* __restrict__ bias,
    float* __restrict__ C, bf16* __restrict__ Chi, bf16* __restrict__ Clo,
    int ldc, float* __restrict__ C2, int Kd)
{
    extern __shared__ uint32_t smw[];
    const uint32_t sb = smem_u32(smw);

    const int tid = threadIdx.x;
    const int lane = tid & 31;
    const int wid = tid >> 5;
    const int warp_m = wid >> 1;
    const int warp_n = wid & 1;
    const int gid = lane >> 2;
    const int tig = lane & 3;
    const int bm = blockIdx.y * 128;
    const int bn = blockIdx.x * 128;

    float acc[2][8][4];
#pragma unroll
    for (int mi = 0; mi < 2; mi++)
#pragma unroll
        for (int nf = 0; nf < 8; nf++)
#pragma unroll
            for (int e = 0; e < 4; e++) acc[mi][nf][e] = 0.f;

    const int lrow = tid >> 1;
    const int lch2 = (tid & 1) * 2;

    auto load_slab = [&](int k0, int s) {
        const bf16 *ahi, *alo; int xld, xc;
        if (k0 < k1) { ahi = X1hi; alo = X1lo; xld = ld1; xc = k0; }
        else         { ahi = X2hi; alo = X2lo; xld = ld2; xc = k0 - k1; }
        const uint32_t st = sb + s * STG_BYTES;
#pragma unroll
        for (int c = 0; c < 2; c++) {
            int ch = lch2 + c;
            uint32_t so = (uint32_t)(lrow * PADW + ch * 4) * 4;
            const size_t ga = (size_t)(bm + lrow) * xld + xc + ch * 8;
            const size_t gw = (size_t)(bn + lrow) * Kd + k0 + ch * 8;
            cp16(st + so,                  ahi + ga);
            cp16(st + TILE_BYTES + so,     alo + ga);
            cp16(st + 2 * TILE_BYTES + so, Whi + gw);
            cp16(st + 3 * TILE_BYTES + so, Wlo + gw);
        }
    };

    int s = 0;
    load_slab(0, 0);
    CP_COMMIT();

#pragma unroll 1
    for (int k0 = 0; k0 < Kd; k0 += 32) {
        if (k0 + 32 < Kd) {
            load_slab(k0 + 32, s ^ 1);
            CP_COMMIT();
            CP_WAIT(1);
        } else {
            CP_WAIT(0);
        }
        __syncthreads();

        const uint32_t* sA  = smw + s * STG_WORDS;
        const uint32_t* sAl = sA + TILE_WORDS;
        const uint32_t* sB  = sA + 2 * TILE_WORDS;
        const uint32_t* sBl = sA + 3 * TILE_WORDS;

#pragma unroll
        for (int h = 0; h < 2; h++) {
            const int kb = h * 8 + tig;
            uint32_t ah[2][4], al[2][4];
#pragma unroll
            for (int mi = 0; mi < 2; mi++) {
                int am = (warp_m * 32 + mi * 16 + gid) * PADW;
                ah[mi][0] = sA [am + kb];
                ah[mi][1] = sA [am + 8 * PADW + kb];
                ah[mi][2] = sA [am + kb + 4];
                ah[mi][3] = sA [am + 8 * PADW + kb + 4];
                al[mi][0] = sAl[am + kb];
                al[mi][1] = sAl[am + 8 * PADW + kb];
                al[mi][2] = sAl[am + kb + 4];
                al[mi][3] = sAl[am + 8 * PADW + kb + 4];
            }
            uint32_t bf[8][2];
#pragma unroll
            for (int nf = 0; nf < 8; nf++) {
                int an = (warp_n * 64 + nf * 8 + gid) * PADW;
                bf[nf][0] = sB[an + kb];
                bf[nf][1] = sB[an + kb + 4];
            }
            // hh sweep: 16 independent accumulators back-to-back
#pragma unroll
            for (int mi = 0; mi < 2; mi++)
#pragma unroll
                for (int nf = 0; nf < 8; nf++)
                    mma16(acc[mi][nf], ah[mi], bf[nf]);
            // lh sweep: each same-acc MMA now 16 insts downstream -> latency hidden
#pragma unroll
            for (int mi = 0; mi < 2; mi++)
#pragma unroll
                for (int nf = 0; nf < 8; nf++)
                    mma16(acc[mi][nf], al[mi], bf[nf]);
            // hl sweep
#pragma unroll
            for (int nf = 0; nf < 8; nf++) {
                int an = (warp_n * 64 + nf * 8 + gid) * PADW;
                bf[nf][0] = sBl[an + kb];
                bf[nf][1] = sBl[an + kb + 4];
            }
#pragma unroll
            for (int mi = 0; mi < 2; mi++)
#pragma unroll
                for (int nf = 0; nf < 8; nf++)
                    mma16(acc[mi][nf], ah[mi], bf[nf]);
        }
        __syncthreads();
        s ^= 1;
    }

    // ---- epilogue ----
    float* outp = C; int oldc = ldc, ncol0 = bn;
    if (OUTM == 2) {
        if (bn >= 256) { outp = C2; oldc = 128; ncol0 = bn - 256; }
        else           { outp = C;  oldc = 256; ncol0 = bn; }
    }

#pragma unroll
    for (int mi = 0; mi < 2; mi++) {
        int r0 = bm + warp_m * 32 + mi * 16 + gid;
#pragma unroll
        for (int nf = 0; nf < 8; nf++) {
            int cg = bn + warp_n * 64 + nf * 8 + tig * 2;
            int cl = ncol0 + warp_n * 64 + nf * 8 + tig * 2;
            float b0 = 0.f, b1 = 0.f;
            if (bias) { float2 bv = *(const float2*)(bias + cg); b0 = bv.x; b1 = bv.y; }
            float v00 = acc[mi][nf][0] + b0;
            float v01 = acc[mi][nf][1] + b1;
            float v10 = acc[mi][nf][2] + b0;
            float v11 = acc[mi][nf][3] + b1;
            if (ACT == 1) {
                v00 = (v00 > 0.f) ? v00 : (__expf(v00) - 1.f);
                v01 = (v01 > 0.f) ? v01 : (__expf(v01) - 1.f);
                v10 = (v10 > 0.f) ? v10 : (__expf(v10) - 1.f);
                v11 = (v11 > 0.f) ? v11 : (__expf(v11) - 1.f);
            }
            if (OUTM == 1) {
                bf16 h, l;
                __nv_bfloat162 ph0, pl0, ph1, pl1;
                bf16split(v00, h, l); ph0.x = h; pl0.x = l;
                bf16split(v01, h, l); ph0.y = h; pl0.y = l;
                bf16split(v10, h, l); ph1.x = h; pl1.x = l;
                bf16split(v11, h, l); ph1.y = h; pl1.y = l;
                *(__nv_bfloat162*)(Chi + (size_t)r0 * ldc + cl)       = ph0;
                *(__nv_bfloat162*)(Clo + (size_t)r0 * ldc + cl)       = pl0;
                *(__nv_bfloat162*)(Chi + (size_t)(r0 + 8) * ldc + cl) = ph1;
                *(__nv_bfloat162*)(Clo + (size_t)(r0 + 8) * ldc + cl) = pl1;
            } else {
                *(float2*)(outp + (size_t)r0 * oldc + cl)       = make_float2(v00, v01);
                *(float2*)(outp + (size_t)(r0 + 8) * oldc + cl) = make_float2(v10, v11);
            }
        }
    }
}

// ---------------- split / prep kernels ----------------
// vectorized: 4 floats per thread
__global__ void split_f32v(const float4* __restrict__ src, __nv_bfloat162* __restrict__ hi,
                           __nv_bfloat162* __restrict__ lo, int n4) {
    int idx = blockIdx.x * blockDim.x + threadIdx.x;
    if (idx >= n4) return;
    float4 v = src[idx];
    bf16 h, l;
    __nv_bfloat162 h0, l0, h1, l1;
    bf16split(v.x, h, l); h0.x = h; l0.x = l;
    bf16split(v.y, h, l); h0.y = h; l0.y = l;
    bf16split(v.z, h, l); h1.x = h; l1.x = l;
    bf16split(v.w, h, l); h1.y = h; l1.y = l;
    hi[idx * 2]     = h0; lo[idx * 2]     = l0;
    hi[idx * 2 + 1] = h1; lo[idx * 2 + 1] = l1;
}

__global__ void prep_wuv(const float* __restrict__ We) {
    int idx = blockIdx.x * blockDim.x + threadIdx.x;
    if (idx >= 1024 * 128) return;
    int n = idx >> 7, c = idx & 127;
    float v;
    if (n < 512) v = We[n * 512 + c] + We[n * 512 + 128 + c];
    else {
        int nn = n - 512;
        v = We[nn * 512 + 256 + c] + We[nn * 512 + 384 + c];
    }
    bf16 h, l; bf16split(v, h, l);
    g_WUV_hi[idx] = h; g_WUV_lo[idx] = l;
}

__global__ void prep_wc(const float* __restrict__ Wc) {
    int idx = blockIdx.x * blockDim.x + threadIdx.x;
    if (idx >= 128 * 640) return;
    int n = idx / 640, c = idx % 640;
    float v = (c < 128) ? (Wc[n * 768 + c] + Wc[n * 768 + 128 + c])
                        : Wc[n * 768 + 128 + c];
    bf16 h, l; bf16split(v, h, l);
    g_WcE_hi[idx] = h; g_WcE_lo[idx] = l;
}

__global__ void prep_wstk(const float* __restrict__ Wl, const float* __restrict__ bl,
                          const float* __restrict__ Wsc, const float* __restrict__ bs,
                          const float* __restrict__ Wh, const float* __restrict__ bh) {
    int idx = blockIdx.x * blockDim.x + threadIdx.x;
    if (idx < 384 * 128) {
        int n = idx >> 7, c = idx & 127;
        const float* W = (n < 128) ? Wl : ((n < 256) ? Wsc : Wh);
        bf16 h, l; bf16split(W[(n & 127) * 128 + c], h, l);
        g_Wstk_hi[idx] = h; g_Wstk_lo[idx] = l;
    }
    if (idx < 384) {
        const float* bb = (idx < 128) ? bl : ((idx < 256) ? bs : bh);
        g_bstk[idx] = bb[idx & 127];
    }
}

// ---------------- GRU gate fusion (writes split h) ----------------
__device__ __forceinline__ float sigm(float x) { return 1.f / (1.f + __expf(-x)); }

__global__ void gru_gate(const float* __restrict__ gi, const float* __restrict__ gh,
                         const float* __restrict__ h0,
                         bf16* __restrict__ hhi, bf16* __restrict__ hlo) {
    int idx = blockIdx.x * blockDim.x + threadIdx.x;
    if (idx >= ROWS * 128) return;
    int m = idx >> 7, c = idx & 127;
    const float* gim = gi + (size_t)m * 384;
    const float* ghm = gh + (size_t)m * 384;
    float r = sigm(gim[c] + ghm[c]);
    float u = sigm(gim[128 + c] + ghm[128 + c]);
    float n = tanhf(gim[256 + c] + r * ghm[256 + c]);
    float v = (1.f - u) * n + u * h0[idx];
    bf16 h, l; bf16split(v, h, l);
    hhi[idx] = h; hlo[idx] = l;
}

// ---------------- pair stage: warp-per-object, atomic-free ----------------
__global__ void __launch_bounds__(512) pair_kernel(
    const float* __restrict__ UV, const float* __restrict__ Wa,
    const float* __restrict__ ba, const float* __restrict__ be,
    bf16* __restrict__ Ehi, bf16* __restrict__ Elo)
{
    extern __shared__ float smf[];
    float* Ub = smf;                 // 16*512
    float* Vb = Ub + 16 * 512;       // 16*512

    const int b = blockIdx.x;
    const int tid = threadIdx.x;
    const int w = tid >> 5, lane = tid & 31;

    for (int i = tid; i < 16 * 512; i += 512) {
        int k = i >> 9, t = i & 511;
        const float* row = UV + (size_t)(b * 16 + k) * 1024;
        Ub[i] = row[t];
        Vb[i] = row[512 + t];
    }
    __syncthreads();

    const float ba0 = __ldg(&ba[0]);
    float uw[16], vw[16], ber[16], war[16], Ew[16];
#pragma unroll
    for (int c = 0; c < 16; c++) {
        int t = lane + 32 * c;
        uw[c] = Ub[w * 512 + t];
        vw[c] = Vb[w * 512 + t];
        ber[c] = __ldg(&be[t]);
        war[c] = __ldg(&Wa[t]);
        Ew[c] = 0.f;
    }

#pragma unroll 1
    for (int o = 0; o < K_OBJ; o++) {
        if (o == w) continue;
        const float* Urow = Ub + o * 512;
        const float* Vrow = Vb + o * 512;
        float e[16];
        float dot = 0.f;
        if (o > w) {
#pragma unroll
            for (int c = 0; c < 16; c++) {
                float x = uw[c] + Vrow[lane + 32 * c] + ber[c];
                x = (x > 0.f) ? x : (__expf(x) - 1.f);
                e[c] = x;
                dot += x * war[c];
            }
        } else {
#pragma unroll
            for (int c = 0; c < 16; c++) {
                float x = Urow[lane + 32 * c] + vw[c] + ber[c];
                x = (x > 0.f) ? x : (__expf(x) - 1.f);
                e[c] = x;
                dot += x * war[c];
            }
        }
#pragma unroll
        for (int off = 16; off > 0; off >>= 1) dot += __shfl_xor_sync(0xffffffffu, dot, off);
        float att = 1.f / (1.f + __expf(-(dot + ba0)));
#pragma unroll
        for (int c = 0; c < 16; c++) Ew[c] += att * e[c];
    }

    bf16* Eh = Ehi + ((size_t)b * 16 + w) * 512;
    bf16* El = Elo + ((size_t)b * 16 + w) * 512;
#pragma unroll
    for (int c = 0; c < 16; c++) {
        bf16 h, l; bf16split(Ew[c], h, l);
        Eh[lane + 32 * c] = h;
        El[lane + 32 * c] = l;
    }
}

// ---------------- host launcher ----------------
extern "C" void kernel_launch(void* const* d_in, const int* in_sizes, int n_in,
                              void* d_out, int out_size)
{
    const float* z    = (const float*)d_in[0];
    const float* h0   = (const float*)d_in[1];
    const float* W_obj= (const float*)d_in[2];
    const float* b_obj= (const float*)d_in[3];
    const float* Wih  = (const float*)d_in[4];
    const float* bih  = (const float*)d_in[5];
    const float* Whh  = (const float*)d_in[6];
    const float* bhh  = (const float*)d_in[7];
    const float* We   = (const float*)d_in[8];
    const float* be   = (const float*)d_in[9];
    const float* Wa   = (const float*)d_in[10];
    const float* ba   = (const float*)d_in[11];
    const float* Wc   = (const float*)d_in[12];
    const float* bc   = (const float*)d_in[13];
    const float* Wl   = (const float*)d_in[14];
    const float* bl   = (const float*)d_in[15];
    const float* Wsc  = (const float*)d_in[16];
    const float* bs   = (const float*)d_in[17];
    const float* Wh   = (const float*)d_in[18];
    const float* bh   = (const float*)d_in[19];

    float* out1 = (float*)d_out;                 // [ROWS, 256] = concat(loc, scale)
    float* out2 = out1 + (size_t)ROWS * 256;     // [ROWS, 128] = h_out

    bf16 *p_z_hi, *p_z_lo, *p_h0_hi, *p_h0_lo, *p_ze_hi, *p_ze_lo;
    bf16 *p_h_hi, *p_h_lo, *p_E_hi, *p_E_lo, *p_rel_hi, *p_rel_lo;
    float *p_gi, *p_gh, *p_UV, *p_bstk;
    bf16 *p_Wobj_hi, *p_Wobj_lo, *p_Wih_hi, *p_Wih_lo, *p_Whh_hi, *p_Whh_lo;
    bf16 *p_WUV_hi, *p_WUV_lo, *p_WcE_hi, *p_WcE_lo, *p_Wstk_hi, *p_Wstk_lo;

    cudaGetSymbolAddress((void**)&p_z_hi,  g_z_hi);   cudaGetSymbolAddress((void**)&p_z_lo,  g_z_lo);
    cudaGetSymbolAddress((void**)&p_h0_hi, g_h0_hi);  cudaGetSymbolAddress((void**)&p_h0_lo, g_h0_lo);
    cudaGetSymbolAddress((void**)&p_ze_hi, g_ze_hi);  cudaGetSymbolAddress((void**)&p_ze_lo, g_ze_lo);
    cudaGetSymbolAddress((void**)&p_h_hi,  g_h_hi);   cudaGetSymbolAddress((void**)&p_h_lo,  g_h_lo);
    cudaGetSymbolAddress((void**)&p_E_hi,  g_E_hi);   cudaGetSymbolAddress((void**)&p_E_lo,  g_E_lo);
    cudaGetSymbolAddress((void**)&p_rel_hi,g_rel_hi); cudaGetSymbolAddress((void**)&p_rel_lo,g_rel_lo);
    cudaGetSymbolAddress((void**)&p_gi, g_gi);
    cudaGetSymbolAddress((void**)&p_gh, g_gh);
    cudaGetSymbolAddress((void**)&p_UV, g_UV);
    cudaGetSymbolAddress((void**)&p_bstk, g_bstk);
    cudaGetSymbolAddress((void**)&p_Wobj_hi, g_Wobj_hi); cudaGetSymbolAddress((void**)&p_Wobj_lo, g_Wobj_lo);
    cudaGetSymbolAddress((void**)&p_Wih_hi,  g_Wih_hi);  cudaGetSymbolAddress((void**)&p_Wih_lo,  g_Wih_lo);
    cudaGetSymbolAddress((void**)&p_Whh_hi,  g_Whh_hi);  cudaGetSymbolAddress((void**)&p_Whh_lo,  g_Whh_lo);
    cudaGetSymbolAddress((void**)&p_WUV_hi,  g_WUV_hi);  cudaGetSymbolAddress((void**)&p_WUV_lo,  g_WUV_lo);
    cudaGetSymbolAddress((void**)&p_WcE_hi,  g_WcE_hi);  cudaGetSymbolAddress((void**)&p_WcE_lo,  g_WcE_lo);
    cudaGetSymbolAddress((void**)&p_Wstk_hi, g_Wstk_hi); cudaGetSymbolAddress((void**)&p_Wstk_lo, g_Wstk_lo);

    const int SMEM_GEMM = 2 * STG_BYTES;   // 81920
    cudaFuncSetAttribute(gemm_mma<1,1>, cudaFuncAttributeMaxDynamicSharedMemorySize, SMEM_GEMM);
    cudaFuncSetAttribute(gemm_mma<0,0>, cudaFuncAttributeMaxDynamicSharedMemorySize, SMEM_GEMM);
    cudaFuncSetAttribute(gemm_mma<0,1>, cudaFuncAttributeMaxDynamicSharedMemorySize, SMEM_GEMM);
    cudaFuncSetAttribute(gemm_mma<0,2>, cudaFuncAttributeMaxDynamicSharedMemorySize, SMEM_GEMM);

    // input + weight splits
    split_f32v<<<(ROWS * 32 + 255) / 256, 256>>>((const float4*)z,
        (__nv_bfloat162*)p_z_hi, (__nv_bfloat162*)p_z_lo, ROWS * 32);
    split_f32v<<<(ROWS * 32 + 255) / 256, 256>>>((const float4*)h0,
        (__nv_bfloat162*)p_h0_hi, (__nv_bfloat162*)p_h0_lo, ROWS * 32);
    split_f32v<<<(256 * 32 + 255) / 256, 256>>>((const float4*)W_obj,
        (__nv_bfloat162*)p_Wobj_hi, (__nv_bfloat162*)p_Wobj_lo, 256 * 32);
    split_f32v<<<(384 * 64 + 255) / 256, 256>>>((const float4*)Wih,
        (__nv_bfloat162*)p_Wih_hi, (__nv_bfloat162*)p_Wih_lo, 384 * 64);
    split_f32v<<<(384 * 32 + 255) / 256, 256>>>((const float4*)Whh,
        (__nv_bfloat162*)p_Whh_hi, (__nv_bfloat162*)p_Whh_lo, 384 * 32);
    prep_wuv <<<(1024 * 128 + 255) / 256, 256>>>(We);
    prep_wc  <<<(128 * 640 + 255) / 256, 256>>>(Wc);
    prep_wstk<<<(384 * 128 + 255) / 256, 256>>>(Wl, bl, Wsc, bs, Wh, bh);

    const int MB = ROWS / 128;   // 256

    // G1: z_embed = elu(z @ W_obj^T + b_obj) -> split  [ROWS, 256]
    gemm_mma<1,1><<<dim3(2, MB), 256, SMEM_GEMM>>>(
        p_z_hi, p_z_lo, 128, 128, nullptr, nullptr, 0,
        p_Wobj_hi, p_Wobj_lo, b_obj, nullptr, p_ze_hi, p_ze_lo, 256, nullptr, 128);
    // G2a: gi = z_embed @ Wih^T + bih  [ROWS, 384] f32
    gemm_mma<0,0><<<dim3(3, MB), 256, SMEM_GEMM>>>(
        p_ze_hi, p_ze_lo, 256, 256, nullptr, nullptr, 0,
        p_Wih_hi, p_Wih_lo, bih, p_gi, nullptr, nullptr, 384, nullptr, 256);
    // G2b: gh = h0 @ Whh^T + bhh  [ROWS, 384] f32
    gemm_mma<0,0><<<dim3(3, MB), 256, SMEM_GEMM>>>(
        p_h0_hi, p_h0_lo, 128, 128, nullptr, nullptr, 0,
        p_Whh_hi, p_Whh_lo, bhh, p_gh, nullptr, nullptr, 384, nullptr, 128);
    // GRU gates -> h (split)
    gru_gate<<<(ROWS * 128 + 255) / 256, 256>>>(p_gi, p_gh, h0, p_h_hi, p_h_lo);

    // G3: UV = h @ W_UV^T  [ROWS, 1024] f32
    gemm_mma<0,0><<<dim3(8, MB), 256, SMEM_GEMM>>>(
        p_h_hi, p_h_lo, 128, 128, nullptr, nullptr, 0,
        p_WUV_hi, p_WUV_lo, nullptr, p_UV, nullptr, nullptr, 1024, nullptr, 128);

    // pair stage -> E (split) [ROWS, 512], atomic-free
    size_t psmem = (2 * 16 * 512) * sizeof(float);   // 65536
    cudaFuncSetAttribute(pair_kernel, cudaFuncAttributeMaxDynamicSharedMemorySize, (int)psmem);
    pair_kernel<<<B_SZ, 512, psmem>>>(p_UV, Wa, ba, be, p_E_hi, p_E_lo);

    // G4: rel = [h | E] @ WcE^T + bc -> split  [ROWS, 128], Kd=640
    gemm_mma<0,1><<<dim3(1, MB), 256, SMEM_GEMM>>>(
        p_h_hi, p_h_lo, 128, 128, p_E_hi, p_E_lo, 512,
        p_WcE_hi, p_WcE_lo, bc, nullptr, p_rel_hi, p_rel_lo, 128, nullptr, 640);

    // G5: [loc|scale|h_out] = rel @ Wstk^T + bstk, final f32 split outputs
    gemm_mma<0,2><<<dim3(3, MB), 256, SMEM_GEMM>>>(
        p_rel_hi, p_rel_lo, 128, 128, nullptr, nullptr, 0,
        p_Wstk_hi, p_Wstk_lo, p_bstk, out1, nullptr, nullptr, 0, out2, 128);
}

// round 11
// speedup vs baseline: 1.3475x; 1.0202x over previous
#include <cuda_runtime.h>
#include <cuda_bf16.h>
#include <math.h>
#include <stdint.h>

#define B_SZ   2048
#define K_OBJ  16
#define ROWS   (B_SZ * K_OBJ)      // 32768
#define NPAIR  120

typedef __nv_bfloat16 bf16;

// ---------------- scratch (device globals; no allocation allowed) ----------------
__device__ __align__(16) bf16 g_z_hi  [(size_t)ROWS * 128];
__device__ __align__(16) bf16 g_z_lo  [(size_t)ROWS * 128];
__device__ __align__(16) bf16 g_h0_hi [(size_t)ROWS * 128];
__device__ __align__(16) bf16 g_h0_lo [(size_t)ROWS * 128];
__device__ __align__(16) bf16 g_ze_hi [(size_t)ROWS * 256];
__device__ __align__(16) bf16 g_ze_lo [(size_t)ROWS * 256];
__device__ __align__(16) bf16 g_h_hi  [(size_t)ROWS * 128];
__device__ __align__(16) bf16 g_h_lo  [(size_t)ROWS * 128];
__device__ __align__(16) bf16 g_E_hi  [(size_t)ROWS * 512];
__device__ __align__(16) bf16 g_E_lo  [(size_t)ROWS * 512];
__device__ __align__(16) bf16 g_rel_hi[(size_t)ROWS * 128];
__device__ __align__(16) bf16 g_rel_lo[(size_t)ROWS * 128];
__device__ __align__(16) float g_gi [(size_t)ROWS * 384];
__device__ __align__(16) float g_gh [(size_t)ROWS * 384];
__device__ __align__(16) float g_UV [(size_t)ROWS * 1024];
__device__ __align__(16) bf16 g_Wobj_hi[256 * 128],  g_Wobj_lo[256 * 128];
__device__ __align__(16) bf16 g_Wih_hi [384 * 256],  g_Wih_lo [384 * 256];
__device__ __align__(16) bf16 g_Whh_hi [384 * 128],  g_Whh_lo [384 * 128];
__device__ __align__(16) bf16 g_WUV_hi [1024 * 128], g_WUV_lo [1024 * 128];
__device__ __align__(16) bf16 g_WcE_hi [128 * 640],  g_WcE_lo [128 * 640];
__device__ __align__(16) bf16 g_Wstk_hi[384 * 128],  g_Wstk_lo[384 * 128];
__device__ __align__(16) float g_bstk[384];

// ---------------- helpers ----------------
__device__ __forceinline__ void bf16split(float x, bf16& h, bf16& l) {
    h = __float2bfloat16_rn(x);
    l = __float2bfloat16_rn(x - __bfloat162float(h));
}

__device__ __forceinline__ uint32_t smem_u32(const void* p) {
    uint32_t a;
    asm("{ .reg .u64 t; cvta.to.shared.u64 t, %1; cvt.u32.u64 %0, t; }" : "=r"(a) : "l"(p));
    return a;
}

__device__ __forceinline__ void cp16(uint32_t dst, const void* src) {
    asm volatile("cp.async.ca.shared.global [%0], [%1], 16;" :: "r"(dst), "l"(src) : "memory");
}
#define CP_COMMIT() asm volatile("cp.async.commit_group;" ::: "memory")
#define CP_WAIT(n)  asm volatile("cp.async.wait_group %0;" :: "n"(n) : "memory")

__device__ __forceinline__ void mma16(float* d, const uint32_t* a, const uint32_t* b) {
    asm volatile(
        "mma.sync.aligned.m16n8k16.row.col.f32.bf16.bf16.f32 "
        "{%0,%1,%2,%3}, {%4,%5,%6,%7}, {%8,%9}, {%0,%1,%2,%3};"
        : "+f"(d[0]), "+f"(d[1]), "+f"(d[2]), "+f"(d[3])
        : "r"(a[0]), "r"(a[1]), "r"(a[2]), "r"(a[3]), "r"(b[0]), "r"(b[1]));
}

// ---------------- tensor-core bf16x3 NT GEMM, CTA tile 128x64, 3 CTAs/SM ----------------
// 8 warps: warp_m = wid>>1 (4), warp_n = wid&1 (2); warp tile 32(M) x 32(N).
// K-slab 32, 2-stage cp.async ring. PADW=20 row stride -> conflict-free LDS.
// OUTM: 0 = f32 C; 1 = bf16-split (Chi, Clo); 2 = final f32 (n<256 -> C ld256, else C2 ld128).
#define PADW 20
#define A_TW  2560   // 128 * PADW
#define B_TW  1280   //  64 * PADW
#define STG_WORDS 7680   // 2*A_TW + 2*B_TW
#define STG_BYTES (STG_WORDS * 4)

template <int ACT, int OUTM>
__global__ void __launch_bounds__(256, 3) gemm_mma(
    const bf16* __restrict__ X1hi, const bf16* __restrict__ X1lo, int ld1, int k1,
    const bf16* __restrict__ X2hi, const bf16* __restrict__ X2lo, int ld2,
    const bf16* __restrict__ Whi, const bf16* __restrict__ Wlo,
    const float* __restrict__ bias,
    float* __restrict__ C, bf16* __restrict__ Chi, bf16* __restrict__ Clo,
    int ldc, float* __restrict__ C2, int Kd)
{
    extern __shared__ uint32_t smw[];
    const uint32_t sb = smem_u32(smw);

    const int tid = threadIdx.x;
    const int lane = tid & 31;
    const int wid = tid >> 5;
    const int warp_m = wid >> 1;       // 0..3
    const int warp_n = wid & 1;        // 0..1
    const int gid = lane >> 2;
    const int tig = lane & 3;
    const int bm = blockIdx.y * 128;
    const int bn = blockIdx.x * 64;

    float acc[2][4][4];
#pragma unroll
    for (int mi = 0; mi < 2; mi++)
#pragma unroll
        for (int nf = 0; nf < 4; nf++)
#pragma unroll
            for (int e = 0; e < 4; e++) acc[mi][nf][e] = 0.f;

    auto load_slab = [&](int k0, int s) {
        const bf16 *ahi, *alo; int xld, xc;
        if (k0 < k1) { ahi = X1hi; alo = X1lo; xld = ld1; xc = k0; }
        else         { ahi = X2hi; alo = X2lo; xld = ld2; xc = k0 - k1; }
        const uint32_t st = sb + s * STG_BYTES;
        // A: 512 chunks (128 rows x 4), 2 per thread
#pragma unroll
        for (int j = 0; j < 2; j++) {
            int c = tid + j * 256;
            int row = c >> 2, ch = c & 3;
            uint32_t so = (uint32_t)(row * PADW + ch * 4) * 4;
            const size_t ga = (size_t)(bm + row) * xld + xc + ch * 8;
            cp16(st + so,            ahi + ga);
            cp16(st + A_TW * 4 + so, alo + ga);
        }
        // B: 256 chunks (64 rows x 4), 1 per thread
        {
            int row = tid >> 2, ch = tid & 3;
            uint32_t so = (uint32_t)(row * PADW + ch * 4) * 4;
            const size_t gw = (size_t)(bn + row) * Kd + k0 + ch * 8;
            cp16(st + 2 * A_TW * 4 + so,             Whi + gw);
            cp16(st + (2 * A_TW + B_TW) * 4 + so,    Wlo + gw);
        }
    };

    int s = 0;
    load_slab(0, 0);
    CP_COMMIT();

#pragma unroll 1
    for (int k0 = 0; k0 < Kd; k0 += 32) {
        if (k0 + 32 < Kd) {
            load_slab(k0 + 32, s ^ 1);
            CP_COMMIT();
            CP_WAIT(1);
        } else {
            CP_WAIT(0);
        }
        __syncthreads();

        const uint32_t* sA  = smw + s * STG_WORDS;
        const uint32_t* sAl = sA + A_TW;
        const uint32_t* sB  = sA + 2 * A_TW;
        const uint32_t* sBl = sA + 2 * A_TW + B_TW;

#pragma unroll
        for (int h = 0; h < 2; h++) {
            const int kb = h * 8 + tig;
            uint32_t ah[2][4], al[2][4];
#pragma unroll
            for (int mi = 0; mi < 2; mi++) {
                int am = (warp_m * 32 + mi * 16 + gid) * PADW;
                ah[mi][0] = sA [am + kb];
                ah[mi][1] = sA [am + 8 * PADW + kb];
                ah[mi][2] = sA [am + kb + 4];
                ah[mi][3] = sA [am + 8 * PADW + kb + 4];
                al[mi][0] = sAl[am + kb];
                al[mi][1] = sAl[am + 8 * PADW + kb];
                al[mi][2] = sAl[am + kb + 4];
                al[mi][3] = sAl[am + 8 * PADW + kb + 4];
            }
            uint32_t bf[4][2];
#pragma unroll
            for (int nf = 0; nf < 4; nf++) {
                int an = (warp_n * 32 + nf * 8 + gid) * PADW;
                bf[nf][0] = sB[an + kb];
                bf[nf][1] = sB[an + kb + 4];
            }
            // hh sweep (8 independent acc)
#pragma unroll
            for (int mi = 0; mi < 2; mi++)
#pragma unroll
                for (int nf = 0; nf < 4; nf++)
                    mma16(acc[mi][nf], ah[mi], bf[nf]);
            // lh sweep
#pragma unroll
            for (int mi = 0; mi < 2; mi++)
#pragma unroll
                for (int nf = 0; nf < 4; nf++)
                    mma16(acc[mi][nf], al[mi], bf[nf]);
            // hl sweep
#pragma unroll
            for (int nf = 0; nf < 4; nf++) {
                int an = (warp_n * 32 + nf * 8 + gid) * PADW;
                bf[nf][0] = sBl[an + kb];
                bf[nf][1] = sBl[an + kb + 4];
            }
#pragma unroll
            for (int mi = 0; mi < 2; mi++)
#pragma unroll
                for (int nf = 0; nf < 4; nf++)
                    mma16(acc[mi][nf], ah[mi], bf[nf]);
        }
        __syncthreads();
        s ^= 1;
    }

    // ---- epilogue ----
    float* outp = C; int oldc = ldc, ncol0 = bn;
    if (OUTM == 2) {
        if (bn >= 256) { outp = C2; oldc = 128; ncol0 = bn - 256; }
        else           { outp = C;  oldc = 256; ncol0 = bn; }
    }

#pragma unroll
    for (int mi = 0; mi < 2; mi++) {
        int r0 = bm + warp_m * 32 + mi * 16 + gid;
#pragma unroll
        for (int nf = 0; nf < 4; nf++) {
            int cg = bn + warp_n * 32 + nf * 8 + tig * 2;
            int cl = ncol0 + warp_n * 32 + nf * 8 + tig * 2;
            float b0 = 0.f, b1 = 0.f;
            if (bias) { float2 bv = *(const float2*)(bias + cg); b0 = bv.x; b1 = bv.y; }
            float v00 = acc[mi][nf][0] + b0;
            float v01 = acc[mi][nf][1] + b1;
            float v10 = acc[mi][nf][2] + b0;
            float v11 = acc[mi][nf][3] + b1;
            if (ACT == 1) {
                v00 = (v00 > 0.f) ? v00 : (__expf(v00) - 1.f);
                v01 = (v01 > 0.f) ? v01 : (__expf(v01) - 1.f);
                v10 = (v10 > 0.f) ? v10 : (__expf(v10) - 1.f);
                v11 = (v11 > 0.f) ? v11 : (__expf(v11) - 1.f);
            }
            if (OUTM == 1) {
                bf16 h, l;
                __nv_bfloat162 ph0, pl0, ph1, pl1;
                bf16split(v00, h, l); ph0.x = h; pl0.x = l;
                bf16split(v01, h, l); ph0.y = h; pl0.y = l;
                bf16split(v10, h, l); ph1.x = h; pl1.x = l;
                bf16split(v11, h, l); ph1.y = h; pl1.y = l;
                *(__nv_bfloat162*)(Chi + (size_t)r0 * ldc + cl)       = ph0;
                *(__nv_bfloat162*)(Clo + (size_t)r0 * ldc + cl)       = pl0;
                *(__nv_bfloat162*)(Chi + (size_t)(r0 + 8) * ldc + cl) = ph1;
                *(__nv_bfloat162*)(Clo + (size_t)(r0 + 8) * ldc + cl) = pl1;
            } else {
                *(float2*)(outp + (size_t)r0 * oldc + cl)       = make_float2(v00, v01);
                *(float2*)(outp + (size_t)(r0 + 8) * oldc + cl) = make_float2(v10, v11);
            }
        }
    }
}

// ---------------- split / prep kernels ----------------
__global__ void split_f32v(const float4* __restrict__ src, __nv_bfloat162* __restrict__ hi,
                           __nv_bfloat162* __restrict__ lo, int n4) {
    int idx = blockIdx.x * blockDim.x + threadIdx.x;
    if (idx >= n4) return;
    float4 v = src[idx];
    bf16 h, l;
    __nv_bfloat162 h0, l0, h1, l1;
    bf16split(v.x, h, l); h0.x = h; l0.x = l;
    bf16split(v.y, h, l); h0.y = h; l0.y = l;
    bf16split(v.z, h, l); h1.x = h; l1.x = l;
    bf16split(v.w, h, l); h1.y = h; l1.y = l;
    hi[idx * 2]     = h0; lo[idx * 2]     = l0;
    hi[idx * 2 + 1] = h1; lo[idx * 2 + 1] = l1;
}

__global__ void prep_wuv(const float* __restrict__ We) {
    int idx = blockIdx.x * blockDim.x + threadIdx.x;
    if (idx >= 1024 * 128) return;
    int n = idx >> 7, c = idx & 127;
    float v;
    if (n < 512) v = We[n * 512 + c] + We[n * 512 + 128 + c];
    else {
        int nn = n - 512;
        v = We[nn * 512 + 256 + c] + We[nn * 512 + 384 + c];
    }
    bf16 h, l; bf16split(v, h, l);
    g_WUV_hi[idx] = h; g_WUV_lo[idx] = l;
}

__global__ void prep_wc(const float* __restrict__ Wc) {
    int idx = blockIdx.x * blockDim.x + threadIdx.x;
    if (idx >= 128 * 640) return;
    int n = idx / 640, c = idx % 640;
    float v = (c < 128) ? (Wc[n * 768 + c] + Wc[n * 768 + 128 + c])
                        : Wc[n * 768 + 128 + c];
    bf16 h, l; bf16split(v, h, l);
    g_WcE_hi[idx] = h; g_WcE_lo[idx] = l;
}

__global__ void prep_wstk(const float* __restrict__ Wl, const float* __restrict__ bl,
                          const float* __restrict__ Wsc, const float* __restrict__ bs,
                          const float* __restrict__ Wh, const float* __restrict__ bh) {
    int idx = blockIdx.x * blockDim.x + threadIdx.x;
    if (idx < 384 * 128) {
        int n = idx >> 7, c = idx & 127;
        const float* W = (n < 128) ? Wl : ((n < 256) ? Wsc : Wh);
        bf16 h, l; bf16split(W[(n & 127) * 128 + c], h, l);
        g_Wstk_hi[idx] = h; g_Wstk_lo[idx] = l;
    }
    if (idx < 384) {
        const float* bb = (idx < 128) ? bl : ((idx < 256) ? bs : bh);
        g_bstk[idx] = bb[idx & 127];
    }
}

// ---------------- GRU gate fusion (writes split h) ----------------
__device__ __forceinline__ float sigm(float x) { return 1.f / (1.f + __expf(-x)); }

__global__ void gru_gate(const float* __restrict__ gi, const float* __restrict__ gh,
                         const float* __restrict__ h0,
                         bf16* __restrict__ hhi, bf16* __restrict__ hlo) {
    int idx = blockIdx.x * blockDim.x + threadIdx.x;
    if (idx >= ROWS * 128) return;
    int m = idx >> 7, c = idx & 127;
    const float* gim = gi + (size_t)m * 384;
    const float* ghm = gh + (size_t)m * 384;
    float r = sigm(gim[c] + ghm[c]);
    float u = sigm(gim[128 + c] + ghm[128 + c]);
    float n = tanhf(gim[256 + c] + r * ghm[256 + c]);
    float v = (1.f - u) * n + u * h0[idx];
    bf16 h, l; bf16split(v, h, l);
    hhi[idx] = h; hlo[idx] = l;
}

// ---------------- pair stage: warp-per-object, atomic-free ----------------
__global__ void __launch_bounds__(512) pair_kernel(
    const float* __restrict__ UV, const float* __restrict__ Wa,
    const float* __restrict__ ba, const float* __restrict__ be,
    bf16* __restrict__ Ehi, bf16* __restrict__ Elo)
{
    extern __shared__ float smf[];
    float* Ub = smf;                 // 16*512
    float* Vb = Ub + 16 * 512;       // 16*512

    const int b = blockIdx.x;
    const int tid = threadIdx.x;
    const int w = tid >> 5, lane = tid & 31;

    for (int i = tid; i < 16 * 512; i += 512) {
        int k = i >> 9, t = i & 511;
        const float* row = UV + (size_t)(b * 16 + k) * 1024;
        Ub[i] = row[t];
        Vb[i] = row[512 + t];
    }
    __syncthreads();

    const float ba0 = __ldg(&ba[0]);
    float uw[16], vw[16], ber[16], war[16], Ew[16];
#pragma unroll
    for (int c = 0; c < 16; c++) {
        int t = lane + 32 * c;
        uw[c] = Ub[w * 512 + t];
        vw[c] = Vb[w * 512 + t];
        ber[c] = __ldg(&be[t]);
        war[c] = __ldg(&Wa[t]);
        Ew[c] = 0.f;
    }

#pragma unroll 1
    for (int o = 0; o < K_OBJ; o++) {
        if (o == w) continue;
        const float* Urow = Ub + o * 512;
        const float* Vrow = Vb + o * 512;
        float e[16];
        float dot = 0.f;
        if (o > w) {
#pragma unroll
            for (int c = 0; c < 16; c++) {
                float x = uw[c] + Vrow[lane + 32 * c] + ber[c];
                x = (x > 0.f) ? x : (__expf(x) - 1.f);
                e[c] = x;
                dot += x * war[c];
            }
        } else {
#pragma unroll
            for (int c = 0; c < 16; c++) {
                float x = Urow[lane + 32 * c] + vw[c] + ber[c];
                x = (x > 0.f) ? x : (__expf(x) - 1.f);
                e[c] = x;
                dot += x * war[c];
            }
        }
#pragma unroll
        for (int off = 16; off > 0; off >>= 1) dot += __shfl_xor_sync(0xffffffffu, dot, off);
        float att = 1.f / (1.f + __expf(-(dot + ba0)));
#pragma unroll
        for (int c = 0; c < 16; c++) Ew[c] += att * e[c];
    }

    bf16* Eh = Ehi + ((size_t)b * 16 + w) * 512;
    bf16* El = Elo + ((size_t)b * 16 + w) * 512;
#pragma unroll
    for (int c = 0; c < 16; c++) {
        bf16 h, l; bf16split(Ew[c], h, l);
        Eh[lane + 32 * c] = h;
        El[lane + 32 * c] = l;
    }
}

// ---------------- host launcher ----------------
extern "C" void kernel_launch(void* const* d_in, const int* in_sizes, int n_in,
                              void* d_out, int out_size)
{
    const float* z    = (const float*)d_in[0];
    const float* h0   = (const float*)d_in[1];
    const float* W_obj= (const float*)d_in[2];
    const float* b_obj= (const float*)d_in[3];
    const float* Wih  = (const float*)d_in[4];
    const float* bih  = (const float*)d_in[5];
    const float* Whh  = (const float*)d_in[6];
    const float* bhh  = (const float*)d_in[7];
    const float* We   = (const float*)d_in[8];
    const float* be   = (const float*)d_in[9];
    const float* Wa   = (const float*)d_in[10];
    const float* ba   = (const float*)d_in[11];
    const float* Wc   = (const float*)d_in[12];
    const float* bc   = (const float*)d_in[13];
    const float* Wl   = (const float*)d_in[14];
    const float* bl   = (const float*)d_in[15];
    const float* Wsc  = (const float*)d_in[16];
    const float* bs   = (const float*)d_in[17];
    const float* Wh   = (const float*)d_in[18];
    const float* bh   = (const float*)d_in[19];

    float* out1 = (float*)d_out;                 // [ROWS, 256] = concat(loc, scale)
    float* out2 = out1 + (size_t)ROWS * 256;     // [ROWS, 128] = h_out

    bf16 *p_z_hi, *p_z_lo, *p_h0_hi, *p_h0_lo, *p_ze_hi, *p_ze_lo;
    bf16 *p_h_hi, *p_h_lo, *p_E_hi, *p_E_lo, *p_rel_hi, *p_rel_lo;
    float *p_gi, *p_gh, *p_UV, *p_bstk;
    bf16 *p_Wobj_hi, *p_Wobj_lo, *p_Wih_hi, *p_Wih_lo, *p_Whh_hi, *p_Whh_lo;
    bf16 *p_WUV_hi, *p_WUV_lo, *p_WcE_hi, *p_WcE_lo, *p_Wstk_hi, *p_Wstk_lo;

    cudaGetSymbolAddress((void**)&p_z_hi,  g_z_hi);   cudaGetSymbolAddress((void**)&p_z_lo,  g_z_lo);
    cudaGetSymbolAddress((void**)&p_h0_hi, g_h0_hi);  cudaGetSymbolAddress((void**)&p_h0_lo, g_h0_lo);
    cudaGetSymbolAddress((void**)&p_ze_hi, g_ze_hi);  cudaGetSymbolAddress((void**)&p_ze_lo, g_ze_lo);
    cudaGetSymbolAddress((void**)&p_h_hi,  g_h_hi);   cudaGetSymbolAddress((void**)&p_h_lo,  g_h_lo);
    cudaGetSymbolAddress((void**)&p_E_hi,  g_E_hi);   cudaGetSymbolAddress((void**)&p_E_lo,  g_E_lo);
    cudaGetSymbolAddress((void**)&p_rel_hi,g_rel_hi); cudaGetSymbolAddress((void**)&p_rel_lo,g_rel_lo);
    cudaGetSymbolAddress((void**)&p_gi, g_gi);
    cudaGetSymbolAddress((void**)&p_gh, g_gh);
    cudaGetSymbolAddress((void**)&p_UV, g_UV);
    cudaGetSymbolAddress((void**)&p_bstk, g_bstk);
    cudaGetSymbolAddress((void**)&p_Wobj_hi, g_Wobj_hi); cudaGetSymbolAddress((void**)&p_Wobj_lo, g_Wobj_lo);
    cudaGetSymbolAddress((void**)&p_Wih_hi,  g_Wih_hi);  cudaGetSymbolAddress((void**)&p_Wih_lo,  g_Wih_lo);
    cudaGetSymbolAddress((void**)&p_Whh_hi,  g_Whh_hi);  cudaGetSymbolAddress((void**)&p_Whh_lo,  g_Whh_lo);
    cudaGetSymbolAddress((void**)&p_WUV_hi,  g_WUV_hi);  cudaGetSymbolAddress((void**)&p_WUV_lo,  g_WUV_lo);
    cudaGetSymbolAddress((void**)&p_WcE_hi,  g_WcE_hi);  cudaGetSymbolAddress((void**)&p_WcE_lo,  g_WcE_lo);
    cudaGetSymbolAddress((void**)&p_Wstk_hi, g_Wstk_hi); cudaGetSymbolAddress((void**)&p_Wstk_lo, g_Wstk_lo);

    const int SMEM_GEMM = 2 * STG_BYTES;   // 61440
    cudaFuncSetAttribute(gemm_mma<1,1>, cudaFuncAttributeMaxDynamicSharedMemorySize, SMEM_GEMM);
    cudaFuncSetAttribute(gemm_mma<0,0>, cudaFuncAttributeMaxDynamicSharedMemorySize, SMEM_GEMM);
    cudaFuncSetAttribute(gemm_mma<0,1>, cudaFuncAttributeMaxDynamicSharedMemorySize, SMEM_GEMM);
    cudaFuncSetAttribute(gemm_mma<0,2>, cudaFuncAttributeMaxDynamicSharedMemorySize, SMEM_GEMM);

    // input + weight splits
    split_f32v<<<(ROWS * 32 + 255) / 256, 256>>>((const float4*)z,
        (__nv_bfloat162*)p_z_hi, (__nv_bfloat162*)p_z_lo, ROWS * 32);
    split_f32v<<<(ROWS * 32 + 255) / 256, 256>>>((const float4*)h0,
        (__nv_bfloat162*)p_h0_hi, (__nv_bfloat162*)p_h0_lo, ROWS * 32);
    split_f32v<<<(256 * 32 + 255) / 256, 256>>>((const float4*)W_obj,
        (__nv_bfloat162*)p_Wobj_hi, (__nv_bfloat162*)p_Wobj_lo, 256 * 32);
    split_f32v<<<(384 * 64 + 255) / 256, 256>>>((const float4*)Wih,
        (__nv_bfloat162*)p_Wih_hi, (__nv_bfloat162*)p_Wih_lo, 384 * 64);
    split_f32v<<<(384 * 32 + 255) / 256, 256>>>((const float4*)Whh,
        (__nv_bfloat162*)p_Whh_hi, (__nv_bfloat162*)p_Whh_lo, 384 * 32);
    prep_wuv <<<(1024 * 128 + 255) / 256, 256>>>(We);
    prep_wc  <<<(128 * 640 + 255) / 256, 256>>>(Wc);
    prep_wstk<<<(384 * 128 + 255) / 256, 256>>>(Wl, bl, Wsc, bs, Wh, bh);

    const int MB = ROWS / 128;   // 256

    // G1: z_embed = elu(z @ W_obj^T + b_obj) -> split  [ROWS, 256]
    gemm_mma<1,1><<<dim3(4, MB), 256, SMEM_GEMM>>>(
        p_z_hi, p_z_lo, 128, 128, nullptr, nullptr, 0,
        p_Wobj_hi, p_Wobj_lo, b_obj, nullptr, p_ze_hi, p_ze_lo, 256, nullptr, 128);
    // G2a: gi = z_embed @ Wih^T + bih  [ROWS, 384] f32
    gemm_mma<0,0><<<dim3(6, MB), 256, SMEM_GEMM>>>(
        p_ze_hi, p_ze_lo, 256, 256, nullptr, nullptr, 0,
        p_Wih_hi, p_Wih_lo, bih, p_gi, nullptr, nullptr, 384, nullptr, 256);
    // G2b: gh = h0 @ Whh^T + bhh  [ROWS, 384] f32
    gemm_mma<0,0><<<dim3(6, MB), 256, SMEM_GEMM>>>(
        p_h0_hi, p_h0_lo, 128, 128, nullptr, nullptr, 0,
        p_Whh_hi, p_Whh_lo, bhh, p_gh, nullptr, nullptr, 384, nullptr, 128);
    // GRU gates -> h (split)
    gru_gate<<<(ROWS * 128 + 255) / 256, 256>>>(p_gi, p_gh, h0, p_h_hi, p_h_lo);

    // G3: UV = h @ W_UV^T  [ROWS, 1024] f32
    gemm_mma<0,0><<<dim3(16, MB), 256, SMEM_GEMM>>>(
        p_h_hi, p_h_lo, 128, 128, nullptr, nullptr, 0,
        p_WUV_hi, p_WUV_lo, nullptr, p_UV, nullptr, nullptr, 1024, nullptr, 128);

    // pair stage -> E (split) [ROWS, 512], atomic-free
    size_t psmem = (2 * 16 * 512) * sizeof(float);   // 65536
    cudaFuncSetAttribute(pair_kernel, cudaFuncAttributeMaxDynamicSharedMemorySize, (int)psmem);
    pair_kernel<<<B_SZ, 512, psmem>>>(p_UV, Wa, ba, be, p_E_hi, p_E_lo);

    // G4: rel = [h | E] @ WcE^T + bc -> split  [ROWS, 128], Kd=640
    gemm_mma<0,1><<<dim3(2, MB), 256, SMEM_GEMM>>>(
        p_h_hi, p_h_lo, 128, 128, p_E_hi, p_E_lo, 512,
        p_WcE_hi, p_WcE_lo, bc, nullptr, p_rel_hi, p_rel_lo, 128, nullptr, 640);

    // G5: [loc|scale|h_out] = rel @ Wstk^T + bstk, final f32 split outputs
    gemm_mma<0,2><<<dim3(6, MB), 256, SMEM_GEMM>>>(
        p_rel_hi, p_rel_lo, 128, 128, nullptr, nullptr, 0,
        p_Wstk_hi, p_Wstk_lo, p_bstk, out1, nullptr, nullptr, 0, out2, 128);
}

// round 12
// speedup vs baseline: 1.4074x; 1.0445x over previous
#include <cuda_runtime.h>
#include <cuda_bf16.h>
#include <math.h>
#include <stdint.h>

#define B_SZ   2048
#define K_OBJ  16
#define ROWS   (B_SZ * K_OBJ)      // 32768
#define NPAIR  120

typedef __nv_bfloat16 bf16;

// ---------------- scratch (device globals; no allocation allowed) ----------------
__device__ __align__(16) bf16 g_z_hi  [(size_t)ROWS * 128];
__device__ __align__(16) bf16 g_z_lo  [(size_t)ROWS * 128];
__device__ __align__(16) bf16 g_h0_hi [(size_t)ROWS * 128];
__device__ __align__(16) bf16 g_h0_lo [(size_t)ROWS * 128];
__device__ __align__(16) bf16 g_ze_hi [(size_t)ROWS * 256];
__device__ __align__(16) bf16 g_ze_lo [(size_t)ROWS * 256];
__device__ __align__(16) bf16 g_h_hi  [(size_t)ROWS * 128];
__device__ __align__(16) bf16 g_h_lo  [(size_t)ROWS * 128];
__device__ __align__(16) bf16 g_E_hi  [(size_t)ROWS * 512];
__device__ __align__(16) bf16 g_E_lo  [(size_t)ROWS * 512];
__device__ __align__(16) bf16 g_rel_hi[(size_t)ROWS * 128];
__device__ __align__(16) bf16 g_rel_lo[(size_t)ROWS * 128];
__device__ __align__(16) float g_gi [(size_t)ROWS * 384];
__device__ __align__(16) float g_gh [(size_t)ROWS * 384];
__device__ __align__(16) float g_UV [(size_t)ROWS * 1024];
__device__ __align__(16) bf16 g_Wobj_hi[256 * 128],  g_Wobj_lo[256 * 128];
__device__ __align__(16) bf16 g_Wih_hi [384 * 256],  g_Wih_lo [384 * 256];
__device__ __align__(16) bf16 g_Whh_hi [384 * 128],  g_Whh_lo [384 * 128];
__device__ __align__(16) bf16 g_WUV_hi [1024 * 128], g_WUV_lo [1024 * 128];
__device__ __align__(16) bf16 g_WcE_hi [128 * 640],  g_WcE_lo [128 * 640];
__device__ __align__(16) bf16 g_Wstk_hi[384 * 128],  g_Wstk_lo[384 * 128];
__device__ __align__(16) float g_bstk[384];

// ---------------- helpers ----------------
__device__ __forceinline__ void bf16split(float x, bf16& h, bf16& l) {
    h = __float2bfloat16_rn(x);
    l = __float2bfloat16_rn(x - __bfloat162float(h));
}

__device__ __forceinline__ uint32_t smem_u32(const void* p) {
    uint32_t a;
    asm("{ .reg .u64 t; cvta.to.shared.u64 t, %1; cvt.u32.u64 %0, t; }" : "=r"(a) : "l"(p));
    return a;
}

__device__ __forceinline__ void cp16(uint32_t dst, const void* src) {
    asm volatile("cp.async.ca.shared.global [%0], [%1], 16;" :: "r"(dst), "l"(src) : "memory");
}
#define CP_COMMIT() asm volatile("cp.async.commit_group;" ::: "memory")
#define CP_WAIT(n)  asm volatile("cp.async.wait_group %0;" :: "n"(n) : "memory")

__device__ __forceinline__ void mma16(float* d, const uint32_t* a, const uint32_t* b) {
    asm volatile(
        "mma.sync.aligned.m16n8k16.row.col.f32.bf16.bf16.f32 "
        "{%0,%1,%2,%3}, {%4,%5,%6,%7}, {%8,%9}, {%0,%1,%2,%3};"
        : "+f"(d[0]), "+f"(d[1]), "+f"(d[2]), "+f"(d[3])
        : "r"(a[0]), "r"(a[1]), "r"(a[2]), "r"(a[3]), "r"(b[0]), "r"(b[1]));
}

// ---------------- tensor-core bf16x3 NT GEMM, CTA 128x64, 3 CTAs/SM ----------------
// Single barrier per K-slab: warp passing iter-i barrier => all warps finished
// iter i-1 MMAs (program order) => safe to overwrite stage (i+1)&1.
#define PADW 20
#define A_TW  2560   // 128 * PADW
#define B_TW  1280   //  64 * PADW
#define STG_WORDS 7680   // 2*A_TW + 2*B_TW
#define STG_BYTES (STG_WORDS * 4)

template <int ACT, int OUTM>
__global__ void __launch_bounds__(256, 3) gemm_mma(
    const bf16* __restrict__ X1hi, const bf16* __restrict__ X1lo, int ld1, int k1,
    const bf16* __restrict__ X2hi, const bf16* __restrict__ X2lo, int ld2,
    const bf16* __restrict__ Whi, const bf16* __restrict__ Wlo,
    const float* __restrict__ bias,
    float* __restrict__ C, bf16* __restrict__ Chi, bf16* __restrict__ Clo,
    int ldc, float* __restrict__ C2, int Kd)
{
    extern __shared__ uint32_t smw[];
    const uint32_t sb = smem_u32(smw);

    const int tid = threadIdx.x;
    const int lane = tid & 31;
    const int wid = tid >> 5;
    const int warp_m = wid >> 1;       // 0..3
    const int warp_n = wid & 1;        // 0..1
    const int gid = lane >> 2;
    const int tig = lane & 3;
    const int bm = blockIdx.y * 128;
    const int bn = blockIdx.x * 64;

    float acc[2][4][4];
#pragma unroll
    for (int mi = 0; mi < 2; mi++)
#pragma unroll
        for (int nf = 0; nf < 4; nf++)
#pragma unroll
            for (int e = 0; e < 4; e++) acc[mi][nf][e] = 0.f;

    auto load_slab = [&](int k0, int s) {
        const bf16 *ahi, *alo; int xld, xc;
        if (k0 < k1) { ahi = X1hi; alo = X1lo; xld = ld1; xc = k0; }
        else         { ahi = X2hi; alo = X2lo; xld = ld2; xc = k0 - k1; }
        const uint32_t st = sb + s * STG_BYTES;
#pragma unroll
        for (int j = 0; j < 2; j++) {
            int c = tid + j * 256;
            int row = c >> 2, ch = c & 3;
            uint32_t so = (uint32_t)(row * PADW + ch * 4) * 4;
            const size_t ga = (size_t)(bm + row) * xld + xc + ch * 8;
            cp16(st + so,            ahi + ga);
            cp16(st + A_TW * 4 + so, alo + ga);
        }
        {
            int row = tid >> 2, ch = tid & 3;
            uint32_t so = (uint32_t)(row * PADW + ch * 4) * 4;
            const size_t gw = (size_t)(bn + row) * Kd + k0 + ch * 8;
            cp16(st + 2 * A_TW * 4 + so,          Whi + gw);
            cp16(st + (2 * A_TW + B_TW) * 4 + so, Wlo + gw);
        }
    };

    load_slab(0, 0);
    CP_COMMIT();

    const int nIter = Kd >> 5;
#pragma unroll 1
    for (int i = 0; i < nIter; i++) {
        CP_WAIT(0);            // slab i complete (single group outstanding)
        __syncthreads();       // visibility + iter i-1 MMAs all done
        if (i + 1 < nIter) {
            load_slab((i + 1) * 32, (i + 1) & 1);
            CP_COMMIT();       // copy of slab i+1 overlaps MMAs of slab i
        }

        const uint32_t* sA  = smw + (i & 1) * STG_WORDS;
        const uint32_t* sAl = sA + A_TW;
        const uint32_t* sB  = sA + 2 * A_TW;
        const uint32_t* sBl = sA + 2 * A_TW + B_TW;

#pragma unroll
        for (int h = 0; h < 2; h++) {
            const int kb = h * 8 + tig;
            uint32_t ah[2][4], al[2][4];
#pragma unroll
            for (int mi = 0; mi < 2; mi++) {
                int am = (warp_m * 32 + mi * 16 + gid) * PADW;
                ah[mi][0] = sA [am + kb];
                ah[mi][1] = sA [am + 8 * PADW + kb];
                ah[mi][2] = sA [am + kb + 4];
                ah[mi][3] = sA [am + 8 * PADW + kb + 4];
                al[mi][0] = sAl[am + kb];
                al[mi][1] = sAl[am + 8 * PADW + kb];
                al[mi][2] = sAl[am + kb + 4];
                al[mi][3] = sAl[am + 8 * PADW + kb + 4];
            }
            uint32_t bf[4][2];
#pragma unroll
            for (int nf = 0; nf < 4; nf++) {
                int an = (warp_n * 32 + nf * 8 + gid) * PADW;
                bf[nf][0] = sB[an + kb];
                bf[nf][1] = sB[an + kb + 4];
            }
#pragma unroll
            for (int mi = 0; mi < 2; mi++)
#pragma unroll
                for (int nf = 0; nf < 4; nf++)
                    mma16(acc[mi][nf], ah[mi], bf[nf]);
#pragma unroll
            for (int mi = 0; mi < 2; mi++)
#pragma unroll
                for (int nf = 0; nf < 4; nf++)
                    mma16(acc[mi][nf], al[mi], bf[nf]);
#pragma unroll
            for (int nf = 0; nf < 4; nf++) {
                int an = (warp_n * 32 + nf * 8 + gid) * PADW;
                bf[nf][0] = sBl[an + kb];
                bf[nf][1] = sBl[an + kb + 4];
            }
#pragma unroll
            for (int mi = 0; mi < 2; mi++)
#pragma unroll
                for (int nf = 0; nf < 4; nf++)
                    mma16(acc[mi][nf], ah[mi], bf[nf]);
        }
    }

    // ---- epilogue ----
    float* outp = C; int oldc = ldc, ncol0 = bn;
    if (OUTM == 2) {
        if (bn >= 256) { outp = C2; oldc = 128; ncol0 = bn - 256; }
        else           { outp = C;  oldc = 256; ncol0 = bn; }
    }

#pragma unroll
    for (int mi = 0; mi < 2; mi++) {
        int r0 = bm + warp_m * 32 + mi * 16 + gid;
#pragma unroll
        for (int nf = 0; nf < 4; nf++) {
            int cg = bn + warp_n * 32 + nf * 8 + tig * 2;
            int cl = ncol0 + warp_n * 32 + nf * 8 + tig * 2;
            float b0 = 0.f, b1 = 0.f;
            if (bias) { float2 bv = *(const float2*)(bias + cg); b0 = bv.x; b1 = bv.y; }
            float v00 = acc[mi][nf][0] + b0;
            float v01 = acc[mi][nf][1] + b1;
            float v10 = acc[mi][nf][2] + b0;
            float v11 = acc[mi][nf][3] + b1;
            if (ACT == 1) {
                v00 = (v00 > 0.f) ? v00 : (__expf(v00) - 1.f);
                v01 = (v01 > 0.f) ? v01 : (__expf(v01) - 1.f);
                v10 = (v10 > 0.f) ? v10 : (__expf(v10) - 1.f);
                v11 = (v11 > 0.f) ? v11 : (__expf(v11) - 1.f);
            }
            if (OUTM == 1) {
                bf16 h, l;
                __nv_bfloat162 ph0, pl0, ph1, pl1;
                bf16split(v00, h, l); ph0.x = h; pl0.x = l;
                bf16split(v01, h, l); ph0.y = h; pl0.y = l;
                bf16split(v10, h, l); ph1.x = h; pl1.x = l;
                bf16split(v11, h, l); ph1.y = h; pl1.y = l;
                *(__nv_bfloat162*)(Chi + (size_t)r0 * ldc + cl)       = ph0;
                *(__nv_bfloat162*)(Clo + (size_t)r0 * ldc + cl)       = pl0;
                *(__nv_bfloat162*)(Chi + (size_t)(r0 + 8) * ldc + cl) = ph1;
                *(__nv_bfloat162*)(Clo + (size_t)(r0 + 8) * ldc + cl) = pl1;
            } else {
                *(float2*)(outp + (size_t)r0 * oldc + cl)       = make_float2(v00, v01);
                *(float2*)(outp + (size_t)(r0 + 8) * oldc + cl) = make_float2(v10, v11);
            }
        }
    }
}

// ---------------- merged split kernel (z, h0, W_obj, Wih, Whh) ----------------
#define N4_Z   1048576   // ROWS*128/4
#define N4_H0  1048576
#define N4_WO  8192      // 256*128/4
#define N4_WIH 24576     // 384*256/4
#define N4_WHH 12288     // 384*128/4
#define N4_TOT (N4_Z + N4_H0 + N4_WO + N4_WIH + N4_WHH)

__device__ __forceinline__ void split4(const float4* src, bf16* hi, bf16* lo, int i) {
    float4 v = src[i];
    bf16 h, l;
    __nv_bfloat162 h0, l0, h1, l1;
    bf16split(v.x, h, l); h0.x = h; l0.x = l;
    bf16split(v.y, h, l); h0.y = h; l0.y = l;
    bf16split(v.z, h, l); h1.x = h; l1.x = l;
    bf16split(v.w, h, l); h1.y = h; l1.y = l;
    ((__nv_bfloat162*)hi)[i * 2]     = h0; ((__nv_bfloat162*)lo)[i * 2]     = l0;
    ((__nv_bfloat162*)hi)[i * 2 + 1] = h1; ((__nv_bfloat162*)lo)[i * 2 + 1] = l1;
}

__global__ void split_all(const float* __restrict__ z, const float* __restrict__ h0,
                          const float* __restrict__ W_obj, const float* __restrict__ Wih,
                          const float* __restrict__ Whh) {
    int idx = blockIdx.x * blockDim.x + threadIdx.x;
    if (idx >= N4_TOT) return;
    if (idx < N4_Z) {
        split4((const float4*)z, g_z_hi, g_z_lo, idx);
    } else if ((idx -= N4_Z) < N4_H0) {
        split4((const float4*)h0, g_h0_hi, g_h0_lo, idx);
    } else if ((idx -= N4_H0) < N4_WO) {
        split4((const float4*)W_obj, g_Wobj_hi, g_Wobj_lo, idx);
    } else if ((idx -= N4_WO) < N4_WIH) {
        split4((const float4*)Wih, g_Wih_hi, g_Wih_lo, idx);
    } else {
        idx -= N4_WIH;
        split4((const float4*)Whh, g_Whh_hi, g_Whh_lo, idx);
    }
}

// ---------------- merged weight-fold kernel (WUV, WcE, Wstk, bstk) ----------------
#define N_WUV  131072   // 1024*128
#define N_WCE  81920    // 128*640
#define N_WSTK 49152    // 384*128
#define N_PREP (N_WUV + N_WCE + N_WSTK + 384)

__global__ void prep_all(const float* __restrict__ We, const float* __restrict__ Wc,
                         const float* __restrict__ Wl, const float* __restrict__ bl,
                         const float* __restrict__ Wsc, const float* __restrict__ bs,
                         const float* __restrict__ Wh, const float* __restrict__ bh) {
    int idx = blockIdx.x * blockDim.x + threadIdx.x;
    if (idx >= N_PREP) return;
    if (idx < N_WUV) {
        int n = idx >> 7, c = idx & 127;
        float v;
        if (n < 512) v = We[n * 512 + c] + We[n * 512 + 128 + c];
        else {
            int nn = n - 512;
            v = We[nn * 512 + 256 + c] + We[nn * 512 + 384 + c];
        }
        bf16 h, l; bf16split(v, h, l);
        g_WUV_hi[idx] = h; g_WUV_lo[idx] = l;
    } else if ((idx -= N_WUV) < N_WCE) {
        int n = idx / 640, c = idx % 640;
        float v = (c < 128) ? (Wc[n * 768 + c] + Wc[n * 768 + 128 + c])
                            : Wc[n * 768 + 128 + c];
        bf16 h, l; bf16split(v, h, l);
        g_WcE_hi[idx] = h; g_WcE_lo[idx] = l;
    } else if ((idx -= N_WCE) < N_WSTK) {
        int n = idx >> 7, c = idx & 127;
        const float* W = (n < 128) ? Wl : ((n < 256) ? Wsc : Wh);
        bf16 h, l; bf16split(W[(n & 127) * 128 + c], h, l);
        g_Wstk_hi[idx] = h; g_Wstk_lo[idx] = l;
    } else {
        idx -= N_WSTK;
        const float* bb = (idx < 128) ? bl : ((idx < 256) ? bs : bh);
        g_bstk[idx] = bb[idx & 127];
    }
}

// ---------------- GRU gate fusion (float4 vectorized, writes split h) ----------------
__device__ __forceinline__ float sigm(float x) { return 1.f / (1.f + __expf(-x)); }

__global__ void gru_gate(const float* __restrict__ gi, const float* __restrict__ gh,
                         const float* __restrict__ h0,
                         bf16* __restrict__ hhi, bf16* __restrict__ hlo) {
    int idx = blockIdx.x * blockDim.x + threadIdx.x;   // one per 4 channels
    if (idx >= ROWS * 32) return;
    int m = idx >> 5, c4 = (idx & 31) * 4;
    const float* gim = gi + (size_t)m * 384;
    const float* ghm = gh + (size_t)m * 384;
    float4 gir = *(const float4*)(gim + c4);
    float4 giu = *(const float4*)(gim + 128 + c4);
    float4 gin = *(const float4*)(gim + 256 + c4);
    float4 ghr = *(const float4*)(ghm + c4);
    float4 ghu = *(const float4*)(ghm + 128 + c4);
    float4 ghn = *(const float4*)(ghm + 256 + c4);
    float4 h0v = *(const float4*)(h0 + (size_t)m * 128 + c4);
    float out[4];
    {
        float r = sigm(gir.x + ghr.x), u = sigm(giu.x + ghu.x);
        out[0] = (1.f - u) * tanhf(gin.x + r * ghn.x) + u * h0v.x;
        r = sigm(gir.y + ghr.y); u = sigm(giu.y + ghu.y);
        out[1] = (1.f - u) * tanhf(gin.y + r * ghn.y) + u * h0v.y;
        r = sigm(gir.z + ghr.z); u = sigm(giu.z + ghu.z);
        out[2] = (1.f - u) * tanhf(gin.z + r * ghn.z) + u * h0v.z;
        r = sigm(gir.w + ghr.w); u = sigm(giu.w + ghu.w);
        out[3] = (1.f - u) * tanhf(gin.w + r * ghn.w) + u * h0v.w;
    }
    __nv_bfloat162 ph0, pl0, ph1, pl1;
    bf16 h, l;
    bf16split(out[0], h, l); ph0.x = h; pl0.x = l;
    bf16split(out[1], h, l); ph0.y = h; pl0.y = l;
    bf16split(out[2], h, l); ph1.x = h; pl1.x = l;
    bf16split(out[3], h, l); ph1.y = h; pl1.y = l;
    __nv_bfloat162* ho = (__nv_bfloat162*)(hhi + (size_t)m * 128 + c4);
    __nv_bfloat162* lo2 = (__nv_bfloat162*)(hlo + (size_t)m * 128 + c4);
    ho[0] = ph0; ho[1] = ph1;
    lo2[0] = pl0; lo2[1] = pl1;
}

// ---------------- pair stage: warp-per-object, atomic-free ----------------
__global__ void __launch_bounds__(512) pair_kernel(
    const float* __restrict__ UV, const float* __restrict__ Wa,
    const float* __restrict__ ba, const float* __restrict__ be,
    bf16* __restrict__ Ehi, bf16* __restrict__ Elo)
{
    extern __shared__ float smf[];
    float* Ub = smf;                 // 16*512
    float* Vb = Ub + 16 * 512;       // 16*512

    const int b = blockIdx.x;
    const int tid = threadIdx.x;
    const int w = tid >> 5, lane = tid & 31;

    for (int i = tid; i < 16 * 512; i += 512) {
        int k = i >> 9, t = i & 511;
        const float* row = UV + (size_t)(b * 16 + k) * 1024;
        Ub[i] = row[t];
        Vb[i] = row[512 + t];
    }
    __syncthreads();

    const float ba0 = __ldg(&ba[0]);
    float uw[16], vw[16], ber[16], war[16], Ew[16];
#pragma unroll
    for (int c = 0; c < 16; c++) {
        int t = lane + 32 * c;
        uw[c] = Ub[w * 512 + t];
        vw[c] = Vb[w * 512 + t];
        ber[c] = __ldg(&be[t]);
        war[c] = __ldg(&Wa[t]);
        Ew[c] = 0.f;
    }

#pragma unroll 1
    for (int o = 0; o < K_OBJ; o++) {
        if (o == w) continue;
        const float* Urow = Ub + o * 512;
        const float* Vrow = Vb + o * 512;
        float e[16];
        float dot = 0.f;
        if (o > w) {
#pragma unroll
            for (int c = 0; c < 16; c++) {
                float x = uw[c] + Vrow[lane + 32 * c] + ber[c];
                x = (x > 0.f) ? x : (__expf(x) - 1.f);
                e[c] = x;
                dot += x * war[c];
            }
        } else {
#pragma unroll
            for (int c = 0; c < 16; c++) {
                float x = Urow[lane + 32 * c] + vw[c] + ber[c];
                x = (x > 0.f) ? x : (__expf(x) - 1.f);
                e[c] = x;
                dot += x * war[c];
            }
        }
#pragma unroll
        for (int off = 16; off > 0; off >>= 1) dot += __shfl_xor_sync(0xffffffffu, dot, off);
        float att = 1.f / (1.f + __expf(-(dot + ba0)));
#pragma unroll
        for (int c = 0; c < 16; c++) Ew[c] += att * e[c];
    }

    bf16* Eh = Ehi + ((size_t)b * 16 + w) * 512;
    bf16* El = Elo + ((size_t)b * 16 + w) * 512;
#pragma unroll
    for (int c = 0; c < 16; c++) {
        bf16 h, l; bf16split(Ew[c], h, l);
        Eh[lane + 32 * c] = h;
        El[lane + 32 * c] = l;
    }
}

// ---------------- host launcher ----------------
extern "C" void kernel_launch(void* const* d_in, const int* in_sizes, int n_in,
                              void* d_out, int out_size)
{
    const float* z    = (const float*)d_in[0];
    const float* h0   = (const float*)d_in[1];
    const float* W_obj= (const float*)d_in[2];
    const float* b_obj= (const float*)d_in[3];
    const float* Wih  = (const float*)d_in[4];
    const float* bih  = (const float*)d_in[5];
    const float* Whh  = (const float*)d_in[6];
    const float* bhh  = (const float*)d_in[7];
    const float* We   = (const float*)d_in[8];
    const float* be   = (const float*)d_in[9];
    const float* Wa   = (const float*)d_in[10];
    const float* ba   = (const float*)d_in[11];
    const float* Wc   = (const float*)d_in[12];
    const float* bc   = (const float*)d_in[13];
    const float* Wl   = (const float*)d_in[14];
    const float* bl   = (const float*)d_in[15];
    const float* Wsc  = (const float*)d_in[16];
    const float* bs   = (const float*)d_in[17];
    const float* Wh   = (const float*)d_in[18];
    const float* bh   = (const float*)d_in[19];

    float* out1 = (float*)d_out;                 // [ROWS, 256] = concat(loc, scale)
    float* out2 = out1 + (size_t)ROWS * 256;     // [ROWS, 128] = h_out

    bf16 *p_z_hi, *p_z_lo, *p_h0_hi, *p_h0_lo, *p_ze_hi, *p_ze_lo;
    bf16 *p_h_hi, *p_h_lo, *p_E_hi, *p_E_lo, *p_rel_hi, *p_rel_lo;
    float *p_gi, *p_gh, *p_UV, *p_bstk;
    bf16 *p_Wobj_hi, *p_Wobj_lo, *p_Wih_hi, *p_Wih_lo, *p_Whh_hi, *p_Whh_lo;
    bf16 *p_WUV_hi, *p_WUV_lo, *p_WcE_hi, *p_WcE_lo, *p_Wstk_hi, *p_Wstk_lo;

    cudaGetSymbolAddress((void**)&p_z_hi,  g_z_hi);   cudaGetSymbolAddress((void**)&p_z_lo,  g_z_lo);
    cudaGetSymbolAddress((void**)&p_h0_hi, g_h0_hi);  cudaGetSymbolAddress((void**)&p_h0_lo, g_h0_lo);
    cudaGetSymbolAddress((void**)&p_ze_hi, g_ze_hi);  cudaGetSymbolAddress((void**)&p_ze_lo, g_ze_lo);
    cudaGetSymbolAddress((void**)&p_h_hi,  g_h_hi);   cudaGetSymbolAddress((void**)&p_h_lo,  g_h_lo);
    cudaGetSymbolAddress((void**)&p_E_hi,  g_E_hi);   cudaGetSymbolAddress((void**)&p_E_lo,  g_E_lo);
    cudaGetSymbolAddress((void**)&p_rel_hi,g_rel_hi); cudaGetSymbolAddress((void**)&p_rel_lo,g_rel_lo);
    cudaGetSymbolAddress((void**)&p_gi, g_gi);
    cudaGetSymbolAddress((void**)&p_gh, g_gh);
    cudaGetSymbolAddress((void**)&p_UV, g_UV);
    cudaGetSymbolAddress((void**)&p_bstk, g_bstk);
    cudaGetSymbolAddress((void**)&p_Wobj_hi, g_Wobj_hi); cudaGetSymbolAddress((void**)&p_Wobj_lo, g_Wobj_lo);
    cudaGetSymbolAddress((void**)&p_Wih_hi,  g_Wih_hi);  cudaGetSymbolAddress((void**)&p_Wih_lo,  g_Wih_lo);
    cudaGetSymbolAddress((void**)&p_Whh_hi,  g_Whh_hi);  cudaGetSymbolAddress((void**)&p_Whh_lo,  g_Whh_lo);
    cudaGetSymbolAddress((void**)&p_WUV_hi,  g_WUV_hi);  cudaGetSymbolAddress((void**)&p_WUV_lo,  g_WUV_lo);
    cudaGetSymbolAddress((void**)&p_WcE_hi,  g_WcE_hi);  cudaGetSymbolAddress((void**)&p_WcE_lo,  g_WcE_lo);
    cudaGetSymbolAddress((void**)&p_Wstk_hi, g_Wstk_hi); cudaGetSymbolAddress((void**)&p_Wstk_lo, g_Wstk_lo);

    const int SMEM_GEMM = 2 * STG_BYTES;   // 61440
    cudaFuncSetAttribute(gemm_mma<1,1>, cudaFuncAttributeMaxDynamicSharedMemorySize, SMEM_GEMM);
    cudaFuncSetAttribute(gemm_mma<0,0>, cudaFuncAttributeMaxDynamicSharedMemorySize, SMEM_GEMM);
    cudaFuncSetAttribute(gemm_mma<0,1>, cudaFuncAttributeMaxDynamicSharedMemorySize, SMEM_GEMM);
    cudaFuncSetAttribute(gemm_mma<0,2>, cudaFuncAttributeMaxDynamicSharedMemorySize, SMEM_GEMM);

    // merged prep launches
    split_all<<<(N4_TOT + 255) / 256, 256>>>(z, h0, W_obj, Wih, Whh);
    prep_all<<<(N_PREP + 255) / 256, 256>>>(We, Wc, Wl, bl, Wsc, bs, Wh, bh);

    const int MB = ROWS / 128;   // 256

    // G1: z_embed = elu(z @ W_obj^T + b_obj) -> split  [ROWS, 256]
    gemm_mma<1,1><<<dim3(4, MB), 256, SMEM_GEMM>>>(
        p_z_hi, p_z_lo, 128, 128, nullptr, nullptr, 0,
        p_Wobj_hi, p_Wobj_lo, b_obj, nullptr, p_ze_hi, p_ze_lo, 256, nullptr, 128);
    // G2a: gi = z_embed @ Wih^T + bih  [ROWS, 384] f32
    gemm_mma<0,0><<<dim3(6, MB), 256, SMEM_GEMM>>>(
        p_ze_hi, p_ze_lo, 256, 256, nullptr, nullptr, 0,
        p_Wih_hi, p_Wih_lo, bih, p_gi, nullptr, nullptr, 384, nullptr, 256);
    // G2b: gh = h0 @ Whh^T + bhh  [ROWS, 384] f32
    gemm_mma<0,0><<<dim3(6, MB), 256, SMEM_GEMM>>>(
        p_h0_hi, p_h0_lo, 128, 128, nullptr, nullptr, 0,
        p_Whh_hi, p_Whh_lo, bhh, p_gh, nullptr, nullptr, 384, nullptr, 128);
    // GRU gates -> h (split)
    gru_gate<<<(ROWS * 32 + 255) / 256, 256>>>(p_gi, p_gh, h0, p_h_hi, p_h_lo);

    // G3: UV = h @ W_UV^T  [ROWS, 1024] f32
    gemm_mma<0,0><<<dim3(16, MB), 256, SMEM_GEMM>>>(
        p_h_hi, p_h_lo, 128, 128, nullptr, nullptr, 0,
        p_WUV_hi, p_WUV_lo, nullptr, p_UV, nullptr, nullptr, 1024, nullptr, 128);

    // pair stage -> E (split) [ROWS, 512], atomic-free
    size_t psmem = (2 * 16 * 512) * sizeof(float);   // 65536
    cudaFuncSetAttribute(pair_kernel, cudaFuncAttributeMaxDynamicSharedMemorySize, (int)psmem);
    pair_kernel<<<B_SZ, 512, psmem>>>(p_UV, Wa, ba, be, p_E_hi, p_E_lo);

    // G4: rel = [h | E] @ WcE^T + bc -> split  [ROWS, 128], Kd=640
    gemm_mma<0,1><<<dim3(2, MB), 256, SMEM_GEMM>>>(
        p_h_hi, p_h_lo, 128, 128, p_E_hi, p_E_lo, 512,
        p_WcE_hi, p_WcE_lo, bc, nullptr, p_rel_hi, p_rel_lo, 128, nullptr, 640);

    // G5: [loc|scale|h_out] = rel @ Wstk^T + bstk, final f32 split outputs
    gemm_mma<0,2><<<dim3(6, MB), 256, SMEM_GEMM>>>(
        p_rel_hi, p_rel_lo, 128, 128, nullptr, nullptr, 0,
        p_Wstk_hi, p_Wstk_lo, p_bstk, out1, nullptr, nullptr, 0, out2, 128);
}